// round 2
// baseline (speedup 1.0000x reference)
#include <cuda_runtime.h>

#define BB 2
#define TT 2048
#define CC 1024
#define HH 16
#define DD 64
#define MM (BB*TT)

#define BQ 32
#define BKV 64

// Scratch (allocation-free): Q, K, V, attention output, each [B*T, C] fp32.
__device__ float g_q[MM*CC];
__device__ float g_k[MM*CC];
__device__ float g_v[MM*CC];
__device__ float g_att[MM*CC];

// ---------------------------------------------------------------------------
// GEMM: Y[M,C] = A[M,C] @ W[C,C] + bias.  64x64 tile, BK=16, 256 threads,
// 4x4 register micro-tile per thread. SEL picks scratch in/out without
// needing cudaGetSymbolAddress on the host side.
//   SEL 0/1/2: A = Ain (x), Y = g_q / g_k / g_v
//   SEL 3    : A = g_att,   Y = Yext (d_out)
// ---------------------------------------------------------------------------
template<int SEL>
__global__ void __launch_bounds__(256) gemm_bias(const float* __restrict__ Ain,
                                                 const float* __restrict__ W,
                                                 const float* __restrict__ bias,
                                                 float* __restrict__ Yext)
{
    const float* A = (SEL == 3) ? g_att : Ain;
    float* Y = (SEL == 0) ? g_q : (SEL == 1) ? g_k : (SEL == 2) ? g_v : Yext;

    __shared__ float As[16][68];   // A tile transposed [k][row], padded (16B-aligned rows)
    __shared__ float Bs[16][64];   // W tile [k][col]

    const int tid = threadIdx.x;
    const int tx = tid & 15;        // 0..15 -> 4 output cols each
    const int ty = tid >> 4;        // 0..15 -> 4 output rows each
    const int rowBase = blockIdx.y * 64;
    const int colBase = blockIdx.x * 64;

    // Global-load assignments (one float4 each per tile)
    const int lr = tid >> 2;        // 0..63  A-tile row
    const int lk = (tid & 3) * 4;   // 0,4,8,12 A-tile k
    const int br = tid >> 4;        // 0..15  B-tile k-row
    const int bc = tx * 4;          // B-tile col

    float acc[4][4];
    #pragma unroll
    for (int i = 0; i < 4; i++)
        #pragma unroll
        for (int j = 0; j < 4; j++) acc[i][j] = 0.f;

    for (int kb = 0; kb < CC; kb += 16) {
        float4 av = *(const float4*)(A + (size_t)(rowBase + lr) * CC + kb + lk);
        float4 bv = *(const float4*)(W + (size_t)(kb + br) * CC + colBase + bc);
        As[lk + 0][lr] = av.x;
        As[lk + 1][lr] = av.y;
        As[lk + 2][lr] = av.z;
        As[lk + 3][lr] = av.w;
        *(float4*)&Bs[br][bc] = bv;
        __syncthreads();

        #pragma unroll
        for (int k = 0; k < 16; k++) {
            float4 a4 = *(const float4*)&As[k][ty * 4];
            float4 b4 = *(const float4*)&Bs[k][tx * 4];
            float aa[4] = {a4.x, a4.y, a4.z, a4.w};
            float bb[4] = {b4.x, b4.y, b4.z, b4.w};
            #pragma unroll
            for (int i = 0; i < 4; i++)
                #pragma unroll
                for (int j = 0; j < 4; j++)
                    acc[i][j] += aa[i] * bb[j];
        }
        __syncthreads();
    }

    float4 bb4 = *(const float4*)(bias + colBase + tx * 4);
    const float bvv[4] = {bb4.x, bb4.y, bb4.z, bb4.w};
    #pragma unroll
    for (int i = 0; i < 4; i++) {
        int row = rowBase + ty * 4 + i;
        float4 o;
        o.x = acc[i][0] + bvv[0];
        o.y = acc[i][1] + bvv[1];
        o.z = acc[i][2] + bvv[2];
        o.w = acc[i][3] + bvv[3];
        *(float4*)(Y + (size_t)row * CC + colBase + tx * 4) = o;
    }
}

// ---------------------------------------------------------------------------
// Causal flash attention, fp32.
// Grid: (T/BQ, H, B). 256 threads = 8 warps; each warp owns 4 query rows.
// Per K/V tile of 64 keys: lane owns keys (lane, lane+32) for scores and
// output columns (lane, lane+32) for PV. K and V are read from smem ONCE
// per warp and reused across the warp's 4 rows (register reuse) so the
// kernel is FMA-bound rather than LDS-bound.
// ---------------------------------------------------------------------------
__global__ void __launch_bounds__(256) attn_kernel()
{
    __shared__ float sQ[BQ][DD];        // 8 KB  (pre-scaled by 1/sqrt(D))
    __shared__ float sKt[DD][BKV];      // 16 KB (transposed: [e][key])
    __shared__ float sV[BKV][DD];       // 16 KB

    const int qb = blockIdx.x * BQ;
    const int h  = blockIdx.y;
    const int b  = blockIdx.z;
    const int tid  = threadIdx.x;
    const int warp = tid >> 5;
    const int lane = tid & 31;

    // Load Q tile (rows qb..qb+31, head slice), pre-scaled by 1/8.
    const float* qptr = g_q + (size_t)(b * TT + qb) * CC + h * DD;
    for (int i = tid; i < BQ * DD / 4; i += 256) {
        int r = i / (DD / 4);
        int c = (i % (DD / 4)) * 4;
        float4 v = *(const float4*)(qptr + (size_t)r * CC + c);
        sQ[r][c + 0] = v.x * 0.125f;
        sQ[r][c + 1] = v.y * 0.125f;
        sQ[r][c + 2] = v.z * 0.125f;
        sQ[r][c + 3] = v.w * 0.125f;
    }

    float m[4], l[4], acc0[4], acc1[4];
    int rowt[4];
    #pragma unroll
    for (int r = 0; r < 4; r++) {
        m[r] = -1e30f; l[r] = 0.f; acc0[r] = 0.f; acc1[r] = 0.f;
        rowt[r] = qb + warp * 4 + r;
    }

    // Causal: only key tiles with kb <= max row index are needed.
    for (int kb = 0; kb < qb + BQ; kb += BKV) {
        __syncthreads();   // protect previous tile's smem reads
        const float* kptr = g_k + (size_t)(b * TT + kb) * CC + h * DD;
        const float* vptr = g_v + (size_t)(b * TT + kb) * CC + h * DD;
        for (int i = tid; i < BKV * DD / 4; i += 256) {
            int r = i / (DD / 4);
            int c = (i % (DD / 4)) * 4;
            float4 kv = *(const float4*)(kptr + (size_t)r * CC + c);
            sKt[c + 0][r] = kv.x;
            sKt[c + 1][r] = kv.y;
            sKt[c + 2][r] = kv.z;
            sKt[c + 3][r] = kv.w;
            *(float4*)&sV[r][c] = *(const float4*)(vptr + (size_t)r * CC + c);
        }
        __syncthreads();

        // ---- scores: e-outer so K regs are reused across 4 rows ----
        float sc0[4], sc1[4];
        #pragma unroll
        for (int r = 0; r < 4; r++) { sc0[r] = 0.f; sc1[r] = 0.f; }
        #pragma unroll 16
        for (int e = 0; e < DD; e++) {
            float k0 = sKt[e][lane];
            float k1 = sKt[e][lane + 32];
            #pragma unroll
            for (int r = 0; r < 4; r++) {
                float qv = sQ[warp * 4 + r][e];   // broadcast
                sc0[r] += qv * k0;
                sc1[r] += qv * k1;
            }
        }

        // ---- online softmax per row ----
        const int s0 = kb + lane, s1 = kb + lane + 32;
        float p0[4], p1[4];
        #pragma unroll
        for (int r = 0; r < 4; r++) {
            float a = (s0 <= rowt[r]) ? sc0[r] : -1e30f;
            float c = (s1 <= rowt[r]) ? sc1[r] : -1e30f;
            float mx = fmaxf(a, c);
            #pragma unroll
            for (int o = 16; o > 0; o >>= 1)
                mx = fmaxf(mx, __shfl_xor_sync(0xffffffffu, mx, o));
            float mnew = fmaxf(m[r], mx);
            float corr = __expf(m[r] - mnew);
            p0[r] = __expf(a - mnew);
            p1[r] = __expf(c - mnew);
            float ps = p0[r] + p1[r];
            #pragma unroll
            for (int o = 16; o > 0; o >>= 1)
                ps += __shfl_xor_sync(0xffffffffu, ps, o);
            l[r] = l[r] * corr + ps;
            acc0[r] *= corr;
            acc1[r] *= corr;
            m[r] = mnew;
        }

        // ---- PV: s-outer so V regs are reused across 4 rows ----
        #pragma unroll 8
        for (int s = 0; s < 32; s++) {
            float v0a = sV[s][lane];
            float v1a = sV[s][lane + 32];
            float v0b = sV[s + 32][lane];
            float v1b = sV[s + 32][lane + 32];
            #pragma unroll
            for (int r = 0; r < 4; r++) {
                float pa = __shfl_sync(0xffffffffu, p0[r], s);
                float pb = __shfl_sync(0xffffffffu, p1[r], s);
                acc0[r] += pa * v0a;
                acc1[r] += pa * v1a;
                acc0[r] += pb * v0b;
                acc1[r] += pb * v1b;
            }
        }
    }

    float* optr = g_att + (size_t)(b * TT + qb) * CC + h * DD;
    #pragma unroll
    for (int r = 0; r < 4; r++) {
        float inv = 1.0f / l[r];
        int rr = warp * 4 + r;
        optr[(size_t)rr * CC + lane]      = acc0[r] * inv;
        optr[(size_t)rr * CC + lane + 32] = acc1[r] * inv;
    }
}

// ---------------------------------------------------------------------------
// Launch: 3 QKV projections -> attention -> output projection.
// All on the default stream; graph-capturable (kernel launches only).
// ---------------------------------------------------------------------------
extern "C" void kernel_launch(void* const* d_in, const int* in_sizes, int n_in,
                              void* d_out, int out_size)
{
    const float* x  = (const float*)d_in[0];
    const float* Wq = (const float*)d_in[1];
    const float* bq = (const float*)d_in[2];
    const float* Wk = (const float*)d_in[3];
    const float* bk = (const float*)d_in[4];
    const float* Wv = (const float*)d_in[5];
    const float* bv = (const float*)d_in[6];
    const float* Wo = (const float*)d_in[7];
    const float* bo = (const float*)d_in[8];
    float* out = (float*)d_out;

    dim3 gg(CC / 64, MM / 64);
    gemm_bias<0><<<gg, 256>>>(x, Wq, bq, nullptr);
    gemm_bias<1><<<gg, 256>>>(x, Wk, bk, nullptr);
    gemm_bias<2><<<gg, 256>>>(x, Wv, bv, nullptr);

    dim3 ga(TT / BQ, HH, BB);
    attn_kernel<<<ga, 256>>>();

    gemm_bias<3><<<gg, 256>>>(x, Wo, bo, out);
}

// round 4
// speedup vs baseline: 1.3759x; 1.3759x over previous
#include <cuda_runtime.h>
#include <cuda_bf16.h>
#include <cstdint>

#define BB 2
#define TT 2048
#define CC 1024
#define HH 16
#define DD 64
#define MM (BB*TT)

#define BQ 32
#define BKV 64

// GEMM tiling
#define BM 128
#define BN 128
#define BK 32
#define PADK 40                    // smem row stride in bf16 (80 B)
#define ROWB (PADK*2)              // 80 bytes
#define AHI_OFF 0
#define ALO_OFF 10240
#define BHI_OFF 20480
#define BLO_OFF 30720
#define STAGE   40960
#define GSMEM_TOTAL (2*STAGE)      // 81920 B

// ---------------------------------------------------------------------------
// Scratch (allocation-free device globals)
// ---------------------------------------------------------------------------
__device__ float g_q[MM*CC];
__device__ float g_k[MM*CC];
__device__ float g_v[MM*CC];
__device__ float g_att[MM*CC];
__device__ __align__(256) __nv_bfloat16 g_xhi[MM*CC];    // split of x / att
__device__ __align__(256) __nv_bfloat16 g_xlo[MM*CC];
__device__ __align__(256) __nv_bfloat16 g_whi[4][CC*CC]; // W transposed [n][k]
__device__ __align__(256) __nv_bfloat16 g_wlo[4][CC*CC];

// ---------------------------------------------------------------------------
// PTX helpers (baseline sm_80+ features only — no 'a'-gated instructions)
// ---------------------------------------------------------------------------
__device__ __forceinline__ uint32_t smem_u32(const void* p) {
    uint32_t a;
    asm("{ .reg .u64 t; cvta.to.shared.u64 t, %1; cvt.u32.u64 %0, t; }" : "=r"(a) : "l"(p));
    return a;
}
__device__ __forceinline__ void cpa16(uint32_t dst, const void* src) {
    asm volatile("cp.async.cg.shared.global [%0], [%1], 16;" :: "r"(dst), "l"(src));
}
__device__ __forceinline__ void cpa_commit() {
    asm volatile("cp.async.commit_group;" ::: "memory");
}
template<int N>
__device__ __forceinline__ void cpa_wait() {
    asm volatile("cp.async.wait_group %0;" :: "n"(N) : "memory");
}
__device__ __forceinline__ void ldsm4(uint32_t* r, uint32_t addr) {
    asm volatile("ldmatrix.sync.aligned.m8n8.x4.shared.b16 {%0,%1,%2,%3}, [%4];"
        : "=r"(r[0]), "=r"(r[1]), "=r"(r[2]), "=r"(r[3]) : "r"(addr));
}
__device__ __forceinline__ void mma16816(float* c, const uint32_t* a,
                                         uint32_t b0, uint32_t b1) {
    asm volatile("mma.sync.aligned.m16n8k16.row.col.f32.bf16.bf16.f32 "
        "{%0,%1,%2,%3}, {%4,%5,%6,%7}, {%8,%9}, {%0,%1,%2,%3};"
        : "+f"(c[0]), "+f"(c[1]), "+f"(c[2]), "+f"(c[3])
        : "r"(a[0]), "r"(a[1]), "r"(a[2]), "r"(a[3]), "r"(b0), "r"(b1));
}

// ---------------------------------------------------------------------------
// Split-convert: fp32 -> bf16 hi + bf16 lo.  ASEL 0: x, ASEL 1: g_att.
// ---------------------------------------------------------------------------
template<int ASEL>
__global__ void __launch_bounds__(256) cvt_split(const float* __restrict__ inArg)
{
    const float* in = (ASEL == 0) ? inArg : g_att;
    size_t i = (size_t)blockIdx.x * 256 + threadIdx.x;
    float4 v = ((const float4*)in)[i];
    float f[4] = {v.x, v.y, v.z, v.w};
    __nv_bfloat16 h[4], l[4];
    #pragma unroll
    for (int j = 0; j < 4; j++) {
        h[j] = __float2bfloat16(f[j]);
        l[j] = __float2bfloat16(f[j] - __bfloat162float(h[j]));
    }
    uint2 uh, ul;
    uh.x = ((uint32_t)*(uint16_t*)&h[1] << 16) | *(uint16_t*)&h[0];
    uh.y = ((uint32_t)*(uint16_t*)&h[3] << 16) | *(uint16_t*)&h[2];
    ul.x = ((uint32_t)*(uint16_t*)&l[1] << 16) | *(uint16_t*)&l[0];
    ul.y = ((uint32_t)*(uint16_t*)&l[3] << 16) | *(uint16_t*)&l[2];
    ((uint2*)g_xhi)[i] = uh;
    ((uint2*)g_xlo)[i] = ul;
}

// ---------------------------------------------------------------------------
// Transpose-convert weights: W[k][n] fp32 -> Wt[n][k] bf16 hi/lo.
// ---------------------------------------------------------------------------
template<int WSEL>
__global__ void __launch_bounds__(256) cvt_wt(const float* __restrict__ W)
{
    __shared__ float t[32][33];
    const int n0 = blockIdx.x * 32, k0 = blockIdx.y * 32;
    const int tx = threadIdx.x & 31, ty = threadIdx.x >> 5;
    #pragma unroll
    for (int i = 0; i < 4; i++)
        t[ty + 8*i][tx] = W[(size_t)(k0 + ty + 8*i) * CC + n0 + tx];
    __syncthreads();
    #pragma unroll
    for (int i = 0; i < 4; i++) {
        int nn = ty + 8*i;
        float v = t[tx][nn];
        __nv_bfloat16 h = __float2bfloat16(v);
        __nv_bfloat16 l = __float2bfloat16(v - __bfloat162float(h));
        g_whi[WSEL][(size_t)(n0 + nn) * CC + k0 + tx] = h;
        g_wlo[WSEL][(size_t)(n0 + nn) * CC + k0 + tx] = l;
    }
}

// ---------------------------------------------------------------------------
// mma.sync bf16-split GEMM:  Y[128x128 tile] = A @ Wt^T + bias
//   A = g_xhi/g_xlo [M,K] K-major,  B = g_whi/g_wlo [N,K] K-major.
//   D += Ah*Bh + Ah*Bl + Al*Bh  (fp32 accum in registers)
// 256 threads = 8 warps (2 m x 4 n), warp tile 64x32, double-buffered cp.async.
// ---------------------------------------------------------------------------
template<int SEL>
__global__ void __launch_bounds__(256) gemm_tc(const float* __restrict__ bias,
                                               float* __restrict__ Yext)
{
    extern __shared__ char sm[];
    const uint32_t smb = smem_u32(sm);
    const int tid  = threadIdx.x;
    const int wid  = tid >> 5;
    const int lane = tid & 31;
    const int warpM = wid >> 2;       // 0..1
    const int warpN = wid & 3;        // 0..3

    const __nv_bfloat16* __restrict__ Ahi = g_xhi;
    const __nv_bfloat16* __restrict__ Alo = g_xlo;
    const __nv_bfloat16* __restrict__ Bhi = g_whi[SEL];
    const __nv_bfloat16* __restrict__ Blo = g_wlo[SEL];
    float* Y = (SEL == 0) ? g_q : (SEL == 1) ? g_k : (SEL == 2) ? g_v : Yext;

    const int rowBase = blockIdx.y * BM;
    const int colBase = blockIdx.x * BN;

    // ldmatrix per-lane byte offsets
    const uint32_t aLane = (uint32_t)((lane & 15) * PADK + (lane >> 4) * 8) * 2;
    const uint32_t bLane = (uint32_t)(((lane & 7) + ((lane >> 4) & 1) * 8) * PADK
                                      + ((lane >> 3) & 1) * 8) * 2;

    float acc[4][4][4];
    #pragma unroll
    for (int i = 0; i < 4; i++)
        #pragma unroll
        for (int j = 0; j < 4; j++)
            #pragma unroll
            for (int r = 0; r < 4; r++) acc[i][j][r] = 0.f;

    // stage loader: 512 16B-chunks per matrix, 2 per thread
    auto stage_load = [&](int s, int buf) {
        const int kb = s * BK;
        const uint32_t base = smb + buf * STAGE;
        #pragma unroll
        for (int i = 0; i < 2; i++) {
            const int idx = tid + i * 256;
            const int row = idx >> 2, ch = idx & 3;
            const uint32_t d = base + (uint32_t)(row * ROWB + ch * 16);
            const size_t ga = (size_t)(rowBase + row) * CC + kb;
            const size_t gb = (size_t)(colBase + row) * CC + kb;
            cpa16(d + AHI_OFF, (const char*)(Ahi + ga) + ch * 16);
            cpa16(d + ALO_OFF, (const char*)(Alo + ga) + ch * 16);
            cpa16(d + BHI_OFF, (const char*)(Bhi + gb) + ch * 16);
            cpa16(d + BLO_OFF, (const char*)(Blo + gb) + ch * 16);
        }
    };

    const int NSTAGE = CC / BK;       // 32
    stage_load(0, 0);
    cpa_commit();

    for (int kt = 0; kt < NSTAGE; kt++) {
        const int buf = kt & 1;
        if (kt + 1 < NSTAGE) {
            stage_load(kt + 1, buf ^ 1);
            cpa_commit();
            cpa_wait<1>();
        } else {
            cpa_wait<0>();
        }
        __syncthreads();

        const uint32_t aBaseHi = smb + buf * STAGE + AHI_OFF
                               + (uint32_t)(warpM * 64 * ROWB) + aLane;
        const uint32_t bBaseHi = smb + buf * STAGE + BHI_OFF
                               + (uint32_t)(warpN * 32 * ROWB) + bLane;

        #pragma unroll
        for (int kk = 0; kk < BK; kk += 16) {
            uint32_t ah[4][4], al[4][4], bh[2][4], bl[2][4];
            #pragma unroll
            for (int mt = 0; mt < 4; mt++) {
                const uint32_t a = aBaseHi + (uint32_t)(mt * 16 * ROWB + kk * 2);
                ldsm4(ah[mt], a);
                ldsm4(al[mt], a + (ALO_OFF - AHI_OFF));
            }
            #pragma unroll
            for (int np = 0; np < 2; np++) {
                const uint32_t b = bBaseHi + (uint32_t)(np * 16 * ROWB + kk * 2);
                ldsm4(bh[np], b);
                ldsm4(bl[np], b + (BLO_OFF - BHI_OFF));
            }
            #pragma unroll
            for (int mt = 0; mt < 4; mt++)
                #pragma unroll
                for (int nt = 0; nt < 4; nt++) {
                    const int np = nt >> 1, s2 = (nt & 1) * 2;
                    mma16816(acc[mt][nt], ah[mt], bh[np][s2], bh[np][s2 + 1]);
                    mma16816(acc[mt][nt], ah[mt], bl[np][s2], bl[np][s2 + 1]);
                    mma16816(acc[mt][nt], al[mt], bh[np][s2], bh[np][s2 + 1]);
                }
        }
        __syncthreads();
    }

    // Epilogue: each lane holds (2 cols) x (2 row-halves) per (mt, nt)
    #pragma unroll
    for (int mt = 0; mt < 4; mt++) {
        const int row = rowBase + warpM * 64 + mt * 16 + (lane >> 2);
        #pragma unroll
        for (int nt = 0; nt < 4; nt++) {
            const int col = colBase + warpN * 32 + nt * 8 + (lane & 3) * 2;
            const float2 b2 = *(const float2*)(bias + col);
            float2 o0, o1;
            o0.x = acc[mt][nt][0] + b2.x;
            o0.y = acc[mt][nt][1] + b2.y;
            o1.x = acc[mt][nt][2] + b2.x;
            o1.y = acc[mt][nt][3] + b2.y;
            *(float2*)(Y + (size_t)row * CC + col)       = o0;
            *(float2*)(Y + (size_t)(row + 8) * CC + col) = o1;
        }
    }
}

// ---------------------------------------------------------------------------
// Causal flash attention, fp32 (unchanged from passing round-1 kernel).
// ---------------------------------------------------------------------------
__global__ void __launch_bounds__(256) attn_kernel()
{
    __shared__ float sQ[BQ][DD];
    __shared__ float sKt[DD][BKV];
    __shared__ float sV[BKV][DD];

    const int qb = blockIdx.x * BQ;
    const int h  = blockIdx.y;
    const int b  = blockIdx.z;
    const int tid  = threadIdx.x;
    const int warp = tid >> 5;
    const int lane = tid & 31;

    const float* qptr = g_q + (size_t)(b * TT + qb) * CC + h * DD;
    for (int i = tid; i < BQ * DD / 4; i += 256) {
        int r = i / (DD / 4);
        int c = (i % (DD / 4)) * 4;
        float4 v = *(const float4*)(qptr + (size_t)r * CC + c);
        sQ[r][c + 0] = v.x * 0.125f;
        sQ[r][c + 1] = v.y * 0.125f;
        sQ[r][c + 2] = v.z * 0.125f;
        sQ[r][c + 3] = v.w * 0.125f;
    }

    float m[4], l[4], acc0[4], acc1[4];
    int rowt[4];
    #pragma unroll
    for (int r = 0; r < 4; r++) {
        m[r] = -1e30f; l[r] = 0.f; acc0[r] = 0.f; acc1[r] = 0.f;
        rowt[r] = qb + warp * 4 + r;
    }

    for (int kb = 0; kb < qb + BQ; kb += BKV) {
        __syncthreads();
        const float* kptr = g_k + (size_t)(b * TT + kb) * CC + h * DD;
        const float* vptr = g_v + (size_t)(b * TT + kb) * CC + h * DD;
        for (int i = tid; i < BKV * DD / 4; i += 256) {
            int r = i / (DD / 4);
            int c = (i % (DD / 4)) * 4;
            float4 kv = *(const float4*)(kptr + (size_t)r * CC + c);
            sKt[c + 0][r] = kv.x;
            sKt[c + 1][r] = kv.y;
            sKt[c + 2][r] = kv.z;
            sKt[c + 3][r] = kv.w;
            *(float4*)&sV[r][c] = *(const float4*)(vptr + (size_t)r * CC + c);
        }
        __syncthreads();

        float sc0[4], sc1[4];
        #pragma unroll
        for (int r = 0; r < 4; r++) { sc0[r] = 0.f; sc1[r] = 0.f; }
        #pragma unroll 16
        for (int e = 0; e < DD; e++) {
            float k0 = sKt[e][lane];
            float k1 = sKt[e][lane + 32];
            #pragma unroll
            for (int r = 0; r < 4; r++) {
                float qv = sQ[warp * 4 + r][e];
                sc0[r] += qv * k0;
                sc1[r] += qv * k1;
            }
        }

        const int s0 = kb + lane, s1 = kb + lane + 32;
        float p0[4], p1[4];
        #pragma unroll
        for (int r = 0; r < 4; r++) {
            float a = (s0 <= rowt[r]) ? sc0[r] : -1e30f;
            float c = (s1 <= rowt[r]) ? sc1[r] : -1e30f;
            float mx = fmaxf(a, c);
            #pragma unroll
            for (int o = 16; o > 0; o >>= 1)
                mx = fmaxf(mx, __shfl_xor_sync(0xffffffffu, mx, o));
            float mnew = fmaxf(m[r], mx);
            float corr = __expf(m[r] - mnew);
            p0[r] = __expf(a - mnew);
            p1[r] = __expf(c - mnew);
            float ps = p0[r] + p1[r];
            #pragma unroll
            for (int o = 16; o > 0; o >>= 1)
                ps += __shfl_xor_sync(0xffffffffu, ps, o);
            l[r] = l[r] * corr + ps;
            acc0[r] *= corr;
            acc1[r] *= corr;
            m[r] = mnew;
        }

        #pragma unroll 8
        for (int s = 0; s < 32; s++) {
            float v0a = sV[s][lane];
            float v1a = sV[s][lane + 32];
            float v0b = sV[s + 32][lane];
            float v1b = sV[s + 32][lane + 32];
            #pragma unroll
            for (int r = 0; r < 4; r++) {
                float pa = __shfl_sync(0xffffffffu, p0[r], s);
                float pb = __shfl_sync(0xffffffffu, p1[r], s);
                acc0[r] += pa * v0a;
                acc1[r] += pa * v1a;
                acc0[r] += pb * v0b;
                acc1[r] += pb * v1b;
            }
        }
    }

    float* optr = g_att + (size_t)(b * TT + qb) * CC + h * DD;
    #pragma unroll
    for (int r = 0; r < 4; r++) {
        float inv = 1.0f / l[r];
        int rr = warp * 4 + r;
        optr[(size_t)rr * CC + lane]      = acc0[r] * inv;
        optr[(size_t)rr * CC + lane + 32] = acc1[r] * inv;
    }
}

// ---------------------------------------------------------------------------
// Launch sequence
// ---------------------------------------------------------------------------
extern "C" void kernel_launch(void* const* d_in, const int* in_sizes, int n_in,
                              void* d_out, int out_size)
{
    const float* x  = (const float*)d_in[0];
    const float* Wq = (const float*)d_in[1];
    const float* bq = (const float*)d_in[2];
    const float* Wk = (const float*)d_in[3];
    const float* bk = (const float*)d_in[4];
    const float* Wv = (const float*)d_in[5];
    const float* bv = (const float*)d_in[6];
    const float* Wo = (const float*)d_in[7];
    const float* bo = (const float*)d_in[8];
    float* out = (float*)d_out;

    cudaFuncSetAttribute(gemm_tc<0>, cudaFuncAttributeMaxDynamicSharedMemorySize, GSMEM_TOTAL);
    cudaFuncSetAttribute(gemm_tc<1>, cudaFuncAttributeMaxDynamicSharedMemorySize, GSMEM_TOTAL);
    cudaFuncSetAttribute(gemm_tc<2>, cudaFuncAttributeMaxDynamicSharedMemorySize, GSMEM_TOTAL);
    cudaFuncSetAttribute(gemm_tc<3>, cudaFuncAttributeMaxDynamicSharedMemorySize, GSMEM_TOTAL);

    const dim3 gcv(MM * CC / 4 / 256);
    const dim3 gtr(CC / 32, CC / 32);
    const dim3 gg(CC / BN, MM / BM);       // 8 x 32

    cvt_split<0><<<gcv, 256>>>(x);
    cvt_wt<0><<<gtr, 256>>>(Wq);
    cvt_wt<1><<<gtr, 256>>>(Wk);
    cvt_wt<2><<<gtr, 256>>>(Wv);
    cvt_wt<3><<<gtr, 256>>>(Wo);

    gemm_tc<0><<<gg, 256, GSMEM_TOTAL>>>(bq, nullptr);
    gemm_tc<1><<<gg, 256, GSMEM_TOTAL>>>(bk, nullptr);
    gemm_tc<2><<<gg, 256, GSMEM_TOTAL>>>(bv, nullptr);

    const dim3 ga(TT / BQ, HH, BB);
    attn_kernel<<<ga, 256>>>();

    cvt_split<1><<<gcv, 256>>>(nullptr);
    gemm_tc<3><<<gg, 256, GSMEM_TOTAL>>>(bo, out);
}

// round 5
// speedup vs baseline: 3.7583x; 2.7314x over previous
#include <cuda_runtime.h>
#include <cuda_bf16.h>
#include <cuda_fp16.h>
#include <cstdint>

#define BB 2
#define TT 2048
#define CC 1024
#define HH 16
#define DD 64
#define MM (BB*TT)

// ---- projection GEMM tiling (unchanged, proven) ----
#define BM 128
#define BN 128
#define BK 32
#define PADK 40
#define ROWB (PADK*2)
#define AHI_OFF 0
#define ALO_OFF 10240
#define BHI_OFF 20480
#define BLO_OFF 30720
#define STAGE   40960
#define GSMEM_TOTAL (2*STAGE)

// ---- attention tiling ----
#define AQ  128                 // q rows per CTA
#define AKV 64                  // kv tile
#define AST 144                 // smem row stride bytes (72 halves): conflict-free ldmatrix
#define SQH 0
#define SQL (128*AST)           // 18432
#define SK0 (2*128*AST)         // 36864
#define SV0 (SK0 + 2*64*AST)    // 55296
#define ASMEM (SV0 + 2*64*AST)  // 73728

#define SCQ (0.125f * 1.44269504088896340736f)   // 1/sqrt(D) * log2(e)

// ---------------------------------------------------------------------------
// Scratch (allocation-free device globals)
// ---------------------------------------------------------------------------
__device__ float g_att[MM*CC];
__device__ __align__(256) __half g_qh[MM*CC];    // Q * 0.125*log2e, hi
__device__ __align__(256) __half g_ql[MM*CC];    // lo residual
__device__ __align__(256) __half g_kh[MM*CC];
__device__ __align__(256) __half g_vh[MM*CC];
__device__ __align__(256) __nv_bfloat16 g_xhi[MM*CC];    // split of x / att
__device__ __align__(256) __nv_bfloat16 g_xlo[MM*CC];
__device__ __align__(256) __nv_bfloat16 g_whi[4][CC*CC]; // W transposed [n][k]
__device__ __align__(256) __nv_bfloat16 g_wlo[4][CC*CC];

// ---------------------------------------------------------------------------
// PTX helpers (baseline sm_80+ features only)
// ---------------------------------------------------------------------------
__device__ __forceinline__ uint32_t smem_u32(const void* p) {
    uint32_t a;
    asm("{ .reg .u64 t; cvta.to.shared.u64 t, %1; cvt.u32.u64 %0, t; }" : "=r"(a) : "l"(p));
    return a;
}
__device__ __forceinline__ void cpa16(uint32_t dst, const void* src) {
    asm volatile("cp.async.cg.shared.global [%0], [%1], 16;" :: "r"(dst), "l"(src));
}
__device__ __forceinline__ void cpa_commit() {
    asm volatile("cp.async.commit_group;" ::: "memory");
}
template<int N>
__device__ __forceinline__ void cpa_wait() {
    asm volatile("cp.async.wait_group %0;" :: "n"(N) : "memory");
}
__device__ __forceinline__ void ldsm4(uint32_t* r, uint32_t addr) {
    asm volatile("ldmatrix.sync.aligned.m8n8.x4.shared.b16 {%0,%1,%2,%3}, [%4];"
        : "=r"(r[0]), "=r"(r[1]), "=r"(r[2]), "=r"(r[3]) : "r"(addr));
}
__device__ __forceinline__ void ldsm4t(uint32_t* r, uint32_t addr) {
    asm volatile("ldmatrix.sync.aligned.m8n8.x4.trans.shared.b16 {%0,%1,%2,%3}, [%4];"
        : "=r"(r[0]), "=r"(r[1]), "=r"(r[2]), "=r"(r[3]) : "r"(addr));
}
__device__ __forceinline__ void mma16816(float* c, const uint32_t* a,
                                         uint32_t b0, uint32_t b1) {
    asm volatile("mma.sync.aligned.m16n8k16.row.col.f32.bf16.bf16.f32 "
        "{%0,%1,%2,%3}, {%4,%5,%6,%7}, {%8,%9}, {%0,%1,%2,%3};"
        : "+f"(c[0]), "+f"(c[1]), "+f"(c[2]), "+f"(c[3])
        : "r"(a[0]), "r"(a[1]), "r"(a[2]), "r"(a[3]), "r"(b0), "r"(b1));
}
__device__ __forceinline__ void mma16816h(float* c, const uint32_t* a,
                                          uint32_t b0, uint32_t b1) {
    asm volatile("mma.sync.aligned.m16n8k16.row.col.f32.f16.f16.f32 "
        "{%0,%1,%2,%3}, {%4,%5,%6,%7}, {%8,%9}, {%0,%1,%2,%3};"
        : "+f"(c[0]), "+f"(c[1]), "+f"(c[2]), "+f"(c[3])
        : "r"(a[0]), "r"(a[1]), "r"(a[2]), "r"(a[3]), "r"(b0), "r"(b1));
}
__device__ __forceinline__ float ex2f(float x) {
    float r;
    asm("ex2.approx.ftz.f32 %0, %1;" : "=f"(r) : "f"(x));
    return r;
}
__device__ __forceinline__ uint32_t packh2(float a, float b) {
    __half2 h = __floats2half2_rn(a, b);
    return *(uint32_t*)&h;
}

// ---------------------------------------------------------------------------
// Split-convert: fp32 -> bf16 hi + bf16 lo.  ASEL 0: x, ASEL 1: g_att.
// ---------------------------------------------------------------------------
template<int ASEL>
__global__ void __launch_bounds__(256) cvt_split(const float* __restrict__ inArg)
{
    const float* in = (ASEL == 0) ? inArg : g_att;
    size_t i = (size_t)blockIdx.x * 256 + threadIdx.x;
    float4 v = ((const float4*)in)[i];
    float f[4] = {v.x, v.y, v.z, v.w};
    __nv_bfloat16 h[4], l[4];
    #pragma unroll
    for (int j = 0; j < 4; j++) {
        h[j] = __float2bfloat16(f[j]);
        l[j] = __float2bfloat16(f[j] - __bfloat162float(h[j]));
    }
    uint2 uh, ul;
    uh.x = ((uint32_t)*(uint16_t*)&h[1] << 16) | *(uint16_t*)&h[0];
    uh.y = ((uint32_t)*(uint16_t*)&h[3] << 16) | *(uint16_t*)&h[2];
    ul.x = ((uint32_t)*(uint16_t*)&l[1] << 16) | *(uint16_t*)&l[0];
    ul.y = ((uint32_t)*(uint16_t*)&l[3] << 16) | *(uint16_t*)&l[2];
    ((uint2*)g_xhi)[i] = uh;
    ((uint2*)g_xlo)[i] = ul;
}

// ---------------------------------------------------------------------------
// Transpose-convert weights: W[k][n] fp32 -> Wt[n][k] bf16 hi/lo.
// ---------------------------------------------------------------------------
template<int WSEL>
__global__ void __launch_bounds__(256) cvt_wt(const float* __restrict__ W)
{
    __shared__ float t[32][33];
    const int n0 = blockIdx.x * 32, k0 = blockIdx.y * 32;
    const int tx = threadIdx.x & 31, ty = threadIdx.x >> 5;
    #pragma unroll
    for (int i = 0; i < 4; i++)
        t[ty + 8*i][tx] = W[(size_t)(k0 + ty + 8*i) * CC + n0 + tx];
    __syncthreads();
    #pragma unroll
    for (int i = 0; i < 4; i++) {
        int nn = ty + 8*i;
        float v = t[tx][nn];
        __nv_bfloat16 h = __float2bfloat16(v);
        __nv_bfloat16 l = __float2bfloat16(v - __bfloat162float(h));
        g_whi[WSEL][(size_t)(n0 + nn) * CC + k0 + tx] = h;
        g_wlo[WSEL][(size_t)(n0 + nn) * CC + k0 + tx] = l;
    }
}

// ---------------------------------------------------------------------------
// mma.sync bf16-split GEMM (proven).  Epilogue per SEL:
//   0 -> g_qh/g_ql fp16 (scaled by 0.125*log2e), 1 -> g_kh, 2 -> g_vh,
//   3 -> Yext fp32.
// ---------------------------------------------------------------------------
template<int SEL>
__global__ void __launch_bounds__(256) gemm_tc(const float* __restrict__ bias,
                                               float* __restrict__ Yext)
{
    extern __shared__ char sm[];
    const uint32_t smb = smem_u32(sm);
    const int tid  = threadIdx.x;
    const int wid  = tid >> 5;
    const int lane = tid & 31;
    const int warpM = wid >> 2;
    const int warpN = wid & 3;

    const __nv_bfloat16* __restrict__ Ahi = g_xhi;
    const __nv_bfloat16* __restrict__ Alo = g_xlo;
    const __nv_bfloat16* __restrict__ Bhi = g_whi[SEL];
    const __nv_bfloat16* __restrict__ Blo = g_wlo[SEL];

    const int rowBase = blockIdx.y * BM;
    const int colBase = blockIdx.x * BN;

    const uint32_t aLane = (uint32_t)((lane & 15) * PADK + (lane >> 4) * 8) * 2;
    const uint32_t bLane = (uint32_t)(((lane & 7) + ((lane >> 4) & 1) * 8) * PADK
                                      + ((lane >> 3) & 1) * 8) * 2;

    float acc[4][4][4];
    #pragma unroll
    for (int i = 0; i < 4; i++)
        #pragma unroll
        for (int j = 0; j < 4; j++)
            #pragma unroll
            for (int r = 0; r < 4; r++) acc[i][j][r] = 0.f;

    auto stage_load = [&](int s, int buf) {
        const int kb = s * BK;
        const uint32_t base = smb + buf * STAGE;
        #pragma unroll
        for (int i = 0; i < 2; i++) {
            const int idx = tid + i * 256;
            const int row = idx >> 2, ch = idx & 3;
            const uint32_t d = base + (uint32_t)(row * ROWB + ch * 16);
            const size_t ga = (size_t)(rowBase + row) * CC + kb;
            const size_t gb = (size_t)(colBase + row) * CC + kb;
            cpa16(d + AHI_OFF, (const char*)(Ahi + ga) + ch * 16);
            cpa16(d + ALO_OFF, (const char*)(Alo + ga) + ch * 16);
            cpa16(d + BHI_OFF, (const char*)(Bhi + gb) + ch * 16);
            cpa16(d + BLO_OFF, (const char*)(Blo + gb) + ch * 16);
        }
    };

    const int NSTAGE = CC / BK;
    stage_load(0, 0);
    cpa_commit();

    for (int kt = 0; kt < NSTAGE; kt++) {
        const int buf = kt & 1;
        if (kt + 1 < NSTAGE) {
            stage_load(kt + 1, buf ^ 1);
            cpa_commit();
            cpa_wait<1>();
        } else {
            cpa_wait<0>();
        }
        __syncthreads();

        const uint32_t aBaseHi = smb + buf * STAGE + AHI_OFF
                               + (uint32_t)(warpM * 64 * ROWB) + aLane;
        const uint32_t bBaseHi = smb + buf * STAGE + BHI_OFF
                               + (uint32_t)(warpN * 32 * ROWB) + bLane;

        #pragma unroll
        for (int kk = 0; kk < BK; kk += 16) {
            uint32_t ah[4][4], al[4][4], bh[2][4], bl[2][4];
            #pragma unroll
            for (int mt = 0; mt < 4; mt++) {
                const uint32_t a = aBaseHi + (uint32_t)(mt * 16 * ROWB + kk * 2);
                ldsm4(ah[mt], a);
                ldsm4(al[mt], a + (ALO_OFF - AHI_OFF));
            }
            #pragma unroll
            for (int np = 0; np < 2; np++) {
                const uint32_t b = bBaseHi + (uint32_t)(np * 16 * ROWB + kk * 2);
                ldsm4(bh[np], b);
                ldsm4(bl[np], b + (BLO_OFF - BHI_OFF));
            }
            #pragma unroll
            for (int mt = 0; mt < 4; mt++)
                #pragma unroll
                for (int nt = 0; nt < 4; nt++) {
                    const int np = nt >> 1, s2 = (nt & 1) * 2;
                    mma16816(acc[mt][nt], ah[mt], bh[np][s2], bh[np][s2 + 1]);
                    mma16816(acc[mt][nt], ah[mt], bl[np][s2], bl[np][s2 + 1]);
                    mma16816(acc[mt][nt], al[mt], bh[np][s2], bh[np][s2 + 1]);
                }
        }
        __syncthreads();
    }

    #pragma unroll
    for (int mt = 0; mt < 4; mt++) {
        const int row = rowBase + warpM * 64 + mt * 16 + (lane >> 2);
        #pragma unroll
        for (int nt = 0; nt < 4; nt++) {
            const int col = colBase + warpN * 32 + nt * 8 + (lane & 3) * 2;
            const float2 b2 = *(const float2*)(bias + col);
            float v00 = acc[mt][nt][0] + b2.x, v01 = acc[mt][nt][1] + b2.y;
            float v10 = acc[mt][nt][2] + b2.x, v11 = acc[mt][nt][3] + b2.y;
            if constexpr (SEL == 3) {
                float2 o0 = {v00, v01}, o1 = {v10, v11};
                *(float2*)(Yext + (size_t)row * CC + col)       = o0;
                *(float2*)(Yext + (size_t)(row + 8) * CC + col) = o1;
            } else if constexpr (SEL == 0) {
                v00 *= SCQ; v01 *= SCQ; v10 *= SCQ; v11 *= SCQ;
                __half2 h0 = __floats2half2_rn(v00, v01);
                __half2 h1 = __floats2half2_rn(v10, v11);
                *(__half2*)(g_qh + (size_t)row * CC + col)       = h0;
                *(__half2*)(g_qh + (size_t)(row + 8) * CC + col) = h1;
                float2 f0 = __half22float2(h0), f1 = __half22float2(h1);
                *(__half2*)(g_ql + (size_t)row * CC + col) =
                    __floats2half2_rn(v00 - f0.x, v01 - f0.y);
                *(__half2*)(g_ql + (size_t)(row + 8) * CC + col) =
                    __floats2half2_rn(v10 - f1.x, v11 - f1.y);
            } else {
                __half* dst = (SEL == 1) ? g_kh : g_vh;
                *(__half2*)(dst + (size_t)row * CC + col)       = __floats2half2_rn(v00, v01);
                *(__half2*)(dst + (size_t)(row + 8) * CC + col) = __floats2half2_rn(v10, v11);
            }
        }
    }
}

// ---------------------------------------------------------------------------
// Tensor-core causal flash attention (fp16 mma, Q split 2-term scores,
// P split 2-term PV).  CTA: 128 q rows, 8 warps x 16 rows, KV tiles of 64.
// ---------------------------------------------------------------------------
__global__ void __launch_bounds__(256) attn_tc()
{
    extern __shared__ char sm[];
    const uint32_t smb = smem_u32(sm);
    const int tid = threadIdx.x, wid = tid >> 5, lane = tid & 31;
    const int qb = (int)(gridDim.x - 1 - blockIdx.x) * AQ;   // heavy CTAs first
    const int h = blockIdx.y, b = blockIdx.z;
    const size_t rowOff = (size_t)(b * TT) * CC + h * DD;

    // ---- load Q tile (hi+lo) + KV tile 0 via cp.async ----
    #pragma unroll
    for (int i = 0; i < 8; i++) {
        int idx = tid + i * 256;                 // 0..2047
        int hl = idx >> 10, r = (idx >> 3) & 127, ch = idx & 7;
        const __half* src = (hl ? g_ql : g_qh) + rowOff + (size_t)(qb + r) * CC + ch * 8;
        cpa16(smb + (hl ? SQL : SQH) + (uint32_t)(r * AST + ch * 16), src);
    }
    auto stageKV = [&](int t, int bufi) {
        int kb = t * AKV;
        #pragma unroll
        for (int i = 0; i < 4; i++) {
            int idx = tid + i * 256;             // 0..1023
            int mv = idx >> 9, r = (idx >> 3) & 63, ch = idx & 7;
            const __half* src = (mv ? g_vh : g_kh) + rowOff + (size_t)(kb + r) * CC + ch * 8;
            cpa16(smb + (mv ? SV0 : SK0) + (uint32_t)(bufi * (64 * AST) + r * AST + ch * 16), src);
        }
    };
    stageKV(0, 0);
    cpa_commit();
    cpa_wait<0>();
    __syncthreads();

    // ---- Q fragments (register resident for whole CTA lifetime) ----
    const uint32_t qlane = (uint32_t)((lane & 15) * AST + (lane >> 4) * 16);
    uint32_t qfh[4][4], qfl[4][4];
    {
        const uint32_t qbase = smb + SQH + (uint32_t)(wid * 16 * AST) + qlane;
        #pragma unroll
        for (int ks = 0; ks < 4; ks++) {
            ldsm4(qfh[ks], qbase + ks * 32);
            ldsm4(qfl[ks], qbase + (SQL - SQH) + ks * 32);
        }
    }

    float O[8][4];
    #pragma unroll
    for (int i = 0; i < 8; i++)
        #pragma unroll
        for (int j = 0; j < 4; j++) O[i][j] = 0.f;
    float m0 = -1e30f, m1 = -1e30f, l0 = 0.f, l1 = 0.f;

    const int wr0 = qb + wid * 16;
    const int ntiles = qb / AKV + 2;
    const uint32_t klane = (uint32_t)(((lane & 7) + ((lane >> 4) & 1) * 8) * AST
                                      + ((lane >> 3) & 1) * 16);
    const uint32_t vlane = (uint32_t)(((lane & 7) + ((lane >> 3) & 1) * 8) * AST
                                      + ((lane >> 4) & 1) * 16);

    for (int t = 0; t < ntiles; t++) {
        const int bufi = t & 1;
        if (t + 1 < ntiles) {
            stageKV(t + 1, bufi ^ 1);
            cpa_commit();
            cpa_wait<1>();
        } else {
            cpa_wait<0>();
        }
        __syncthreads();

        const int kb = t * AKV;
        if (kb <= wr0 + 15) {                    // warp has unmasked rows in this tile
            // ---- scores S = (Qh+Ql) . K^T ----
            float S[8][4];
            #pragma unroll
            for (int i = 0; i < 8; i++)
                #pragma unroll
                for (int j = 0; j < 4; j++) S[i][j] = 0.f;

            const uint32_t kbase = smb + SK0 + (uint32_t)(bufi * (64 * AST)) + klane;
            #pragma unroll
            for (int nn = 0; nn < 4; nn++)
                #pragma unroll
                for (int ks = 0; ks < 4; ks++) {
                    uint32_t kf[4];
                    ldsm4(kf, kbase + (uint32_t)(nn * 16 * AST + ks * 32));
                    mma16816h(S[2*nn],   qfh[ks], kf[0], kf[1]);
                    mma16816h(S[2*nn+1], qfh[ks], kf[2], kf[3]);
                    mma16816h(S[2*nn],   qfl[ks], kf[0], kf[1]);
                    mma16816h(S[2*nn+1], qfl[ks], kf[2], kf[3]);
                }

            // ---- causal mask ----
            if (kb + 63 > wr0) {
                const int r0 = wr0 + (lane >> 2), r1 = r0 + 8;
                #pragma unroll
                for (int sf = 0; sf < 8; sf++) {
                    const int c = kb + sf * 8 + (lane & 3) * 2;
                    if (c     > r0) S[sf][0] = -1e30f;
                    if (c + 1 > r0) S[sf][1] = -1e30f;
                    if (c     > r1) S[sf][2] = -1e30f;
                    if (c + 1 > r1) S[sf][3] = -1e30f;
                }
            }

            // ---- online softmax (log2 domain) ----
            float mx0 = -1e30f, mx1 = -1e30f;
            #pragma unroll
            for (int sf = 0; sf < 8; sf++) {
                mx0 = fmaxf(mx0, fmaxf(S[sf][0], S[sf][1]));
                mx1 = fmaxf(mx1, fmaxf(S[sf][2], S[sf][3]));
            }
            mx0 = fmaxf(mx0, __shfl_xor_sync(0xffffffffu, mx0, 1));
            mx0 = fmaxf(mx0, __shfl_xor_sync(0xffffffffu, mx0, 2));
            mx1 = fmaxf(mx1, __shfl_xor_sync(0xffffffffu, mx1, 1));
            mx1 = fmaxf(mx1, __shfl_xor_sync(0xffffffffu, mx1, 2));
            const float nm0 = fmaxf(m0, mx0), nm1 = fmaxf(m1, mx1);
            const float corr0 = ex2f(m0 - nm0), corr1 = ex2f(m1 - nm1);
            m0 = nm0; m1 = nm1;

            float sum0 = 0.f, sum1 = 0.f;
            #pragma unroll
            for (int sf = 0; sf < 8; sf++) {
                S[sf][0] = ex2f(S[sf][0] - nm0);
                S[sf][1] = ex2f(S[sf][1] - nm0);
                S[sf][2] = ex2f(S[sf][2] - nm1);
                S[sf][3] = ex2f(S[sf][3] - nm1);
                sum0 += S[sf][0] + S[sf][1];
                sum1 += S[sf][2] + S[sf][3];
            }
            sum0 += __shfl_xor_sync(0xffffffffu, sum0, 1);
            sum0 += __shfl_xor_sync(0xffffffffu, sum0, 2);
            sum1 += __shfl_xor_sync(0xffffffffu, sum1, 1);
            sum1 += __shfl_xor_sync(0xffffffffu, sum1, 2);
            l0 = l0 * corr0 + sum0;
            l1 = l1 * corr1 + sum1;

            #pragma unroll
            for (int sf = 0; sf < 8; sf++) {
                O[sf][0] *= corr0; O[sf][1] *= corr0;
                O[sf][2] *= corr1; O[sf][3] *= corr1;
            }

            // ---- pack P into fp16 A-fragments (hi + lo) ----
            uint32_t pa[4][4], pl[4][4];
            #pragma unroll
            for (int j = 0; j < 4; j++) {
                #pragma unroll
                for (int q = 0; q < 4; q++) {
                    const int sf = 2 * j + (q >> 1);
                    const int e  = (q & 1) * 2;
                    const float a = S[sf][e], c = S[sf][e + 1];
                    const uint32_t ph = packh2(a, c);
                    pa[j][q] = ph;
                    const float2 fb = __half22float2(*(const __half2*)&ph);
                    pl[j][q] = packh2(a - fb.x, c - fb.y);
                }
            }
            // reg order fix: A-frag regs = {(r,klo),(r+8,klo),(r,khi),(r+8,khi)}
            //   (r,klo)  = S[2j] c0c1 -> q index 0
            //   (r+8,klo)= S[2j] c2c3 -> q index 1
            //   (r,khi)  = S[2j+1] c0c1 -> q index 2
            //   (r+8,khi)= S[2j+1] c2c3 -> q index 3   (matches loop above)

            // ---- O += (Ph+Pl) . V ----
            const uint32_t vbase = smb + SV0 + (uint32_t)(bufi * (64 * AST)) + vlane;
            #pragma unroll
            for (int dd = 0; dd < 4; dd++)
                #pragma unroll
                for (int j = 0; j < 4; j++) {
                    uint32_t vf[4];
                    ldsm4t(vf, vbase + (uint32_t)(j * 16 * AST + dd * 32));
                    mma16816h(O[2*dd],   pa[j], vf[0], vf[1]);
                    mma16816h(O[2*dd+1], pa[j], vf[2], vf[3]);
                    mma16816h(O[2*dd],   pl[j], vf[0], vf[1]);
                    mma16816h(O[2*dd+1], pl[j], vf[2], vf[3]);
                }
        }
        __syncthreads();
    }

    // ---- epilogue: normalize and store fp32 att output ----
    const float inv0 = 1.f / l0, inv1 = 1.f / l1;
    const int row0 = qb + wid * 16 + (lane >> 2);
    #pragma unroll
    for (int sf = 0; sf < 8; sf++) {
        const int col = h * DD + sf * 8 + (lane & 3) * 2;
        float2 o0 = {O[sf][0] * inv0, O[sf][1] * inv0};
        float2 o1 = {O[sf][2] * inv1, O[sf][3] * inv1};
        *(float2*)(g_att + (size_t)(b * TT + row0) * CC + col)     = o0;
        *(float2*)(g_att + (size_t)(b * TT + row0 + 8) * CC + col) = o1;
    }
}

// ---------------------------------------------------------------------------
// Launch sequence
// ---------------------------------------------------------------------------
extern "C" void kernel_launch(void* const* d_in, const int* in_sizes, int n_in,
                              void* d_out, int out_size)
{
    const float* x  = (const float*)d_in[0];
    const float* Wq = (const float*)d_in[1];
    const float* bq = (const float*)d_in[2];
    const float* Wk = (const float*)d_in[3];
    const float* bk = (const float*)d_in[4];
    const float* Wv = (const float*)d_in[5];
    const float* bv = (const float*)d_in[6];
    const float* Wo = (const float*)d_in[7];
    const float* bo = (const float*)d_in[8];
    float* out = (float*)d_out;

    cudaFuncSetAttribute(gemm_tc<0>, cudaFuncAttributeMaxDynamicSharedMemorySize, GSMEM_TOTAL);
    cudaFuncSetAttribute(gemm_tc<1>, cudaFuncAttributeMaxDynamicSharedMemorySize, GSMEM_TOTAL);
    cudaFuncSetAttribute(gemm_tc<2>, cudaFuncAttributeMaxDynamicSharedMemorySize, GSMEM_TOTAL);
    cudaFuncSetAttribute(gemm_tc<3>, cudaFuncAttributeMaxDynamicSharedMemorySize, GSMEM_TOTAL);
    cudaFuncSetAttribute(attn_tc,    cudaFuncAttributeMaxDynamicSharedMemorySize, ASMEM);

    const dim3 gcv(MM * CC / 4 / 256);
    const dim3 gtr(CC / 32, CC / 32);
    const dim3 gg(CC / BN, MM / BM);

    cvt_split<0><<<gcv, 256>>>(x);
    cvt_wt<0><<<gtr, 256>>>(Wq);
    cvt_wt<1><<<gtr, 256>>>(Wk);
    cvt_wt<2><<<gtr, 256>>>(Wv);
    cvt_wt<3><<<gtr, 256>>>(Wo);

    gemm_tc<0><<<gg, 256, GSMEM_TOTAL>>>(bq, nullptr);
    gemm_tc<1><<<gg, 256, GSMEM_TOTAL>>>(bk, nullptr);
    gemm_tc<2><<<gg, 256, GSMEM_TOTAL>>>(bv, nullptr);

    const dim3 ga(TT / AQ, HH, BB);
    attn_tc<<<ga, 256, ASMEM>>>();

    cvt_split<1><<<gcv, 256>>>(nullptr);
    gemm_tc<3><<<gg, 256, GSMEM_TOTAL>>>(bo, out);
}

// round 6
// speedup vs baseline: 5.1051x; 1.3584x over previous
#include <cuda_runtime.h>
#include <cuda_fp16.h>
#include <cstdint>

#define BB 2
#define TT 2048
#define CC 1024
#define HH 16
#define DD 64
#define MM (BB*TT)

// ---- projection GEMM tiling ----
#define BM 128
#define BN 128
#define BK 32
#define PADK 40                 // smem row stride in halves (80 B)
#define ROWB (PADK*2)
#define AH_OFF 0
#define AL_OFF 10240
#define BH_OFF 20480
#define STAGE3 30720
#define GSMEM_TOTAL (3*STAGE3)  // 92160 B

// ---- attention tiling ----
#define AQ  128
#define AKV 64
#define AST 144
#define SQH 0
#define SQL (128*AST)
#define SK0 (2*128*AST)
#define SV0 (SK0 + 2*64*AST)
#define ASMEM (SV0 + 2*64*AST)  // 73728

#define SCQ (0.125f * 1.44269504088896340736f)   // 1/sqrt(D) * log2(e)

// ---------------------------------------------------------------------------
// Scratch (allocation-free device globals) — all fp16 now
// ---------------------------------------------------------------------------
__device__ __align__(256) __half g_qh[MM*CC];    // Q * 0.125*log2e, hi
__device__ __align__(256) __half g_ql[MM*CC];    // lo residual
__device__ __align__(256) __half g_kh[MM*CC];
__device__ __align__(256) __half g_vh[MM*CC];
__device__ __align__(256) __half g_ah[MM*CC];    // A-operand hi (x, later att out)
__device__ __align__(256) __half g_al[MM*CC];    // A-operand lo
__device__ __align__(256) __half g_wh[4][CC*CC]; // W transposed [n][k], fp16

// ---------------------------------------------------------------------------
// PTX helpers (baseline sm_80+ features only)
// ---------------------------------------------------------------------------
__device__ __forceinline__ uint32_t smem_u32(const void* p) {
    uint32_t a;
    asm("{ .reg .u64 t; cvta.to.shared.u64 t, %1; cvt.u32.u64 %0, t; }" : "=r"(a) : "l"(p));
    return a;
}
__device__ __forceinline__ void cpa16(uint32_t dst, const void* src) {
    asm volatile("cp.async.cg.shared.global [%0], [%1], 16;" :: "r"(dst), "l"(src));
}
__device__ __forceinline__ void cpa_commit() {
    asm volatile("cp.async.commit_group;" ::: "memory");
}
template<int N>
__device__ __forceinline__ void cpa_wait() {
    asm volatile("cp.async.wait_group %0;" :: "n"(N) : "memory");
}
__device__ __forceinline__ void ldsm4(uint32_t* r, uint32_t addr) {
    asm volatile("ldmatrix.sync.aligned.m8n8.x4.shared.b16 {%0,%1,%2,%3}, [%4];"
        : "=r"(r[0]), "=r"(r[1]), "=r"(r[2]), "=r"(r[3]) : "r"(addr));
}
__device__ __forceinline__ void ldsm4t(uint32_t* r, uint32_t addr) {
    asm volatile("ldmatrix.sync.aligned.m8n8.x4.trans.shared.b16 {%0,%1,%2,%3}, [%4];"
        : "=r"(r[0]), "=r"(r[1]), "=r"(r[2]), "=r"(r[3]) : "r"(addr));
}
__device__ __forceinline__ void mma16816h(float* c, const uint32_t* a,
                                          uint32_t b0, uint32_t b1) {
    asm volatile("mma.sync.aligned.m16n8k16.row.col.f32.f16.f16.f32 "
        "{%0,%1,%2,%3}, {%4,%5,%6,%7}, {%8,%9}, {%0,%1,%2,%3};"
        : "+f"(c[0]), "+f"(c[1]), "+f"(c[2]), "+f"(c[3])
        : "r"(a[0]), "r"(a[1]), "r"(a[2]), "r"(a[3]), "r"(b0), "r"(b1));
}
__device__ __forceinline__ float ex2f(float x) {
    float r;
    asm("ex2.approx.ftz.f32 %0, %1;" : "=f"(r) : "f"(x));
    return r;
}
__device__ __forceinline__ uint32_t packh2(float a, float b) {
    __half2 h = __floats2half2_rn(a, b);
    return *(uint32_t*)&h;
}

// ---------------------------------------------------------------------------
// Split-convert x: fp32 -> fp16 hi + fp16 lo into g_ah/g_al.
// ---------------------------------------------------------------------------
__global__ void __launch_bounds__(256) cvt_split_x(const float* __restrict__ in)
{
    size_t i = (size_t)blockIdx.x * 256 + threadIdx.x;   // float4 index
    float4 v = ((const float4*)in)[i];
    float f[4] = {v.x, v.y, v.z, v.w};
    __half h[4], l[4];
    #pragma unroll
    for (int j = 0; j < 4; j++) {
        h[j] = __float2half(f[j]);
        l[j] = __float2half(f[j] - __half2float(h[j]));
    }
    uint2 uh, ul;
    uh.x = ((uint32_t)*(uint16_t*)&h[1] << 16) | *(uint16_t*)&h[0];
    uh.y = ((uint32_t)*(uint16_t*)&h[3] << 16) | *(uint16_t*)&h[2];
    ul.x = ((uint32_t)*(uint16_t*)&l[1] << 16) | *(uint16_t*)&l[0];
    ul.y = ((uint32_t)*(uint16_t*)&l[3] << 16) | *(uint16_t*)&l[2];
    ((uint2*)g_ah)[i] = uh;
    ((uint2*)g_al)[i] = ul;
}

// ---------------------------------------------------------------------------
// Transpose-convert all 4 weights: W[k][n] fp32 -> g_wh[z][n][k] fp16.
// ---------------------------------------------------------------------------
__global__ void __launch_bounds__(256) cvt_wt_all(const float* __restrict__ W0,
                                                  const float* __restrict__ W1,
                                                  const float* __restrict__ W2,
                                                  const float* __restrict__ W3)
{
    const float* Ws[4] = {W0, W1, W2, W3};
    const float* W = Ws[blockIdx.z];
    __half* dst = g_wh[blockIdx.z];
    __shared__ float t[32][33];
    const int n0 = blockIdx.x * 32, k0 = blockIdx.y * 32;
    const int tx = threadIdx.x & 31, ty = threadIdx.x >> 5;
    #pragma unroll
    for (int i = 0; i < 4; i++)
        t[ty + 8*i][tx] = W[(size_t)(k0 + ty + 8*i) * CC + n0 + tx];
    __syncthreads();
    #pragma unroll
    for (int i = 0; i < 4; i++) {
        int nn = ty + 8*i;
        dst[(size_t)(n0 + nn) * CC + k0 + tx] = __float2half(t[tx][nn]);
    }
}

// ---------------------------------------------------------------------------
// fp16 2-term GEMM:  Y[128x128 tile] = (Ah+Al) @ Wh^T + bias
// QKV=true: grid.z selects q/k/v (bias0/1/2; epilogue to g_qh+g_ql / g_kh / g_vh)
// QKV=false: single O-projection, fp32 epilogue to Yext.
// 256 threads = 8 warps (2m x 4n), warp tile 64x32, 3-stage cp.async pipeline.
// ---------------------------------------------------------------------------
template<bool QKV>
__global__ void __launch_bounds__(256) gemm_fp16(const float* __restrict__ bias0,
                                                 const float* __restrict__ bias1,
                                                 const float* __restrict__ bias2,
                                                 float* __restrict__ Yext)
{
    extern __shared__ char sm[];
    const uint32_t smb = smem_u32(sm);
    const int tid  = threadIdx.x;
    const int wid  = tid >> 5;
    const int lane = tid & 31;
    const int warpM = wid >> 2;
    const int warpN = wid & 3;
    const int z = QKV ? (int)blockIdx.z : 3;

    const __half* __restrict__ Ah = g_ah;
    const __half* __restrict__ Al = g_al;
    const __half* __restrict__ Bh = g_wh[z];
    const float* bias = QKV ? (z == 0 ? bias0 : z == 1 ? bias1 : bias2) : bias0;

    const int rowBase = blockIdx.y * BM;
    const int colBase = blockIdx.x * BN;

    const uint32_t aLane = (uint32_t)((lane & 15) * PADK + (lane >> 4) * 8) * 2;
    const uint32_t bLane = (uint32_t)(((lane & 7) + ((lane >> 4) & 1) * 8) * PADK
                                      + ((lane >> 3) & 1) * 8) * 2;

    float acc[4][4][4];
    #pragma unroll
    for (int i = 0; i < 4; i++)
        #pragma unroll
        for (int j = 0; j < 4; j++)
            #pragma unroll
            for (int r = 0; r < 4; r++) acc[i][j][r] = 0.f;

    auto stage_load = [&](int s, int buf) {
        const int kb = s * BK;
        const uint32_t base = smb + buf * STAGE3;
        #pragma unroll
        for (int i = 0; i < 2; i++) {
            const int idx = tid + i * 256;
            const int row = idx >> 2, ch = idx & 3;
            const uint32_t d = base + (uint32_t)(row * ROWB + ch * 16);
            const size_t ga = (size_t)(rowBase + row) * CC + kb;
            const size_t gb = (size_t)(colBase + row) * CC + kb;
            cpa16(d + AH_OFF, (const char*)(Ah + ga) + ch * 16);
            cpa16(d + AL_OFF, (const char*)(Al + ga) + ch * 16);
            cpa16(d + BH_OFF, (const char*)(Bh + gb) + ch * 16);
        }
    };

    const int NSTAGE = CC / BK;       // 32
    stage_load(0, 0); cpa_commit();
    stage_load(1, 1); cpa_commit();

    int buf = 0;
    for (int kt = 0; kt < NSTAGE; kt++) {
        if (kt + 2 < NSTAGE) {
            int nb = buf + 2; if (nb >= 3) nb -= 3;
            stage_load(kt + 2, nb);
            cpa_commit();
            cpa_wait<2>();
        } else if (kt + 1 < NSTAGE) {
            cpa_wait<1>();
        } else {
            cpa_wait<0>();
        }
        __syncthreads();

        const uint32_t aBase = smb + buf * STAGE3 + AH_OFF
                             + (uint32_t)(warpM * 64 * ROWB) + aLane;
        const uint32_t bBase = smb + buf * STAGE3 + BH_OFF
                             + (uint32_t)(warpN * 32 * ROWB) + bLane;

        #pragma unroll
        for (int kk = 0; kk < BK; kk += 16) {
            uint32_t ah[4][4], al[4][4], bh[2][4];
            #pragma unroll
            for (int mt = 0; mt < 4; mt++) {
                const uint32_t a = aBase + (uint32_t)(mt * 16 * ROWB + kk * 2);
                ldsm4(ah[mt], a);
                ldsm4(al[mt], a + (AL_OFF - AH_OFF));
            }
            #pragma unroll
            for (int np = 0; np < 2; np++)
                ldsm4(bh[np], bBase + (uint32_t)(np * 16 * ROWB + kk * 2));
            #pragma unroll
            for (int mt = 0; mt < 4; mt++)
                #pragma unroll
                for (int nt = 0; nt < 4; nt++) {
                    const int np = nt >> 1, s2 = (nt & 1) * 2;
                    mma16816h(acc[mt][nt], ah[mt], bh[np][s2], bh[np][s2 + 1]);
                    mma16816h(acc[mt][nt], al[mt], bh[np][s2], bh[np][s2 + 1]);
                }
        }
        __syncthreads();
        buf++; if (buf == 3) buf = 0;
    }

    #pragma unroll
    for (int mt = 0; mt < 4; mt++) {
        const int row = rowBase + warpM * 64 + mt * 16 + (lane >> 2);
        #pragma unroll
        for (int nt = 0; nt < 4; nt++) {
            const int col = colBase + warpN * 32 + nt * 8 + (lane & 3) * 2;
            const float2 b2 = *(const float2*)(bias + col);
            float v00 = acc[mt][nt][0] + b2.x, v01 = acc[mt][nt][1] + b2.y;
            float v10 = acc[mt][nt][2] + b2.x, v11 = acc[mt][nt][3] + b2.y;
            if constexpr (!QKV) {
                float2 o0 = {v00, v01}, o1 = {v10, v11};
                *(float2*)(Yext + (size_t)row * CC + col)       = o0;
                *(float2*)(Yext + (size_t)(row + 8) * CC + col) = o1;
            } else {
                if (z == 0) {
                    v00 *= SCQ; v01 *= SCQ; v10 *= SCQ; v11 *= SCQ;
                    __half2 h0 = __floats2half2_rn(v00, v01);
                    __half2 h1 = __floats2half2_rn(v10, v11);
                    *(__half2*)(g_qh + (size_t)row * CC + col)       = h0;
                    *(__half2*)(g_qh + (size_t)(row + 8) * CC + col) = h1;
                    float2 f0 = __half22float2(h0), f1 = __half22float2(h1);
                    *(__half2*)(g_ql + (size_t)row * CC + col) =
                        __floats2half2_rn(v00 - f0.x, v01 - f0.y);
                    *(__half2*)(g_ql + (size_t)(row + 8) * CC + col) =
                        __floats2half2_rn(v10 - f1.x, v11 - f1.y);
                } else {
                    __half* dst = (z == 1) ? g_kh : g_vh;
                    *(__half2*)(dst + (size_t)row * CC + col)       = __floats2half2_rn(v00, v01);
                    *(__half2*)(dst + (size_t)(row + 8) * CC + col) = __floats2half2_rn(v10, v11);
                }
            }
        }
    }
}

// ---------------------------------------------------------------------------
// Tensor-core causal flash attention (fp16 mma, Q split 2-term scores,
// P split 2-term PV).  Epilogue writes fp16 hi/lo directly into g_ah/g_al
// (A-operand of the output projection) — no fp32 pass.
// ---------------------------------------------------------------------------
__global__ void __launch_bounds__(256) attn_tc()
{
    extern __shared__ char sm[];
    const uint32_t smb = smem_u32(sm);
    const int tid = threadIdx.x, wid = tid >> 5, lane = tid & 31;
    const int qb = (int)(gridDim.x - 1 - blockIdx.x) * AQ;   // heavy CTAs first
    const int h = blockIdx.y, b = blockIdx.z;
    const size_t rowOff = (size_t)(b * TT) * CC + h * DD;

    #pragma unroll
    for (int i = 0; i < 8; i++) {
        int idx = tid + i * 256;
        int hl = idx >> 10, r = (idx >> 3) & 127, ch = idx & 7;
        const __half* src = (hl ? g_ql : g_qh) + rowOff + (size_t)(qb + r) * CC + ch * 8;
        cpa16(smb + (hl ? SQL : SQH) + (uint32_t)(r * AST + ch * 16), src);
    }
    auto stageKV = [&](int t, int bufi) {
        int kb = t * AKV;
        #pragma unroll
        for (int i = 0; i < 4; i++) {
            int idx = tid + i * 256;
            int mv = idx >> 9, r = (idx >> 3) & 63, ch = idx & 7;
            const __half* src = (mv ? g_vh : g_kh) + rowOff + (size_t)(kb + r) * CC + ch * 8;
            cpa16(smb + (mv ? SV0 : SK0) + (uint32_t)(bufi * (64 * AST) + r * AST + ch * 16), src);
        }
    };
    stageKV(0, 0);
    cpa_commit();
    cpa_wait<0>();
    __syncthreads();

    const uint32_t qlane = (uint32_t)((lane & 15) * AST + (lane >> 4) * 16);
    uint32_t qfh[4][4], qfl[4][4];
    {
        const uint32_t qbase = smb + SQH + (uint32_t)(wid * 16 * AST) + qlane;
        #pragma unroll
        for (int ks = 0; ks < 4; ks++) {
            ldsm4(qfh[ks], qbase + ks * 32);
            ldsm4(qfl[ks], qbase + (SQL - SQH) + ks * 32);
        }
    }

    float O[8][4];
    #pragma unroll
    for (int i = 0; i < 8; i++)
        #pragma unroll
        for (int j = 0; j < 4; j++) O[i][j] = 0.f;
    float m0 = -1e30f, m1 = -1e30f, l0 = 0.f, l1 = 0.f;

    const int wr0 = qb + wid * 16;
    const int ntiles = qb / AKV + 2;
    const uint32_t klane = (uint32_t)(((lane & 7) + ((lane >> 4) & 1) * 8) * AST
                                      + ((lane >> 3) & 1) * 16);
    const uint32_t vlane = (uint32_t)(((lane & 7) + ((lane >> 3) & 1) * 8) * AST
                                      + ((lane >> 4) & 1) * 16);

    for (int t = 0; t < ntiles; t++) {
        const int bufi = t & 1;
        if (t + 1 < ntiles) {
            stageKV(t + 1, bufi ^ 1);
            cpa_commit();
            cpa_wait<1>();
        } else {
            cpa_wait<0>();
        }
        __syncthreads();

        const int kb = t * AKV;
        if (kb <= wr0 + 15) {
            float S[8][4];
            #pragma unroll
            for (int i = 0; i < 8; i++)
                #pragma unroll
                for (int j = 0; j < 4; j++) S[i][j] = 0.f;

            const uint32_t kbase = smb + SK0 + (uint32_t)(bufi * (64 * AST)) + klane;
            #pragma unroll
            for (int nn = 0; nn < 4; nn++)
                #pragma unroll
                for (int ks = 0; ks < 4; ks++) {
                    uint32_t kf[4];
                    ldsm4(kf, kbase + (uint32_t)(nn * 16 * AST + ks * 32));
                    mma16816h(S[2*nn],   qfh[ks], kf[0], kf[1]);
                    mma16816h(S[2*nn+1], qfh[ks], kf[2], kf[3]);
                    mma16816h(S[2*nn],   qfl[ks], kf[0], kf[1]);
                    mma16816h(S[2*nn+1], qfl[ks], kf[2], kf[3]);
                }

            if (kb + 63 > wr0) {
                const int r0 = wr0 + (lane >> 2), r1 = r0 + 8;
                #pragma unroll
                for (int sf = 0; sf < 8; sf++) {
                    const int c = kb + sf * 8 + (lane & 3) * 2;
                    if (c     > r0) S[sf][0] = -1e30f;
                    if (c + 1 > r0) S[sf][1] = -1e30f;
                    if (c     > r1) S[sf][2] = -1e30f;
                    if (c + 1 > r1) S[sf][3] = -1e30f;
                }
            }

            float mx0 = -1e30f, mx1 = -1e30f;
            #pragma unroll
            for (int sf = 0; sf < 8; sf++) {
                mx0 = fmaxf(mx0, fmaxf(S[sf][0], S[sf][1]));
                mx1 = fmaxf(mx1, fmaxf(S[sf][2], S[sf][3]));
            }
            mx0 = fmaxf(mx0, __shfl_xor_sync(0xffffffffu, mx0, 1));
            mx0 = fmaxf(mx0, __shfl_xor_sync(0xffffffffu, mx0, 2));
            mx1 = fmaxf(mx1, __shfl_xor_sync(0xffffffffu, mx1, 1));
            mx1 = fmaxf(mx1, __shfl_xor_sync(0xffffffffu, mx1, 2));
            const float nm0 = fmaxf(m0, mx0), nm1 = fmaxf(m1, mx1);
            const float corr0 = ex2f(m0 - nm0), corr1 = ex2f(m1 - nm1);
            m0 = nm0; m1 = nm1;

            float sum0 = 0.f, sum1 = 0.f;
            #pragma unroll
            for (int sf = 0; sf < 8; sf++) {
                S[sf][0] = ex2f(S[sf][0] - nm0);
                S[sf][1] = ex2f(S[sf][1] - nm0);
                S[sf][2] = ex2f(S[sf][2] - nm1);
                S[sf][3] = ex2f(S[sf][3] - nm1);
                sum0 += S[sf][0] + S[sf][1];
                sum1 += S[sf][2] + S[sf][3];
            }
            sum0 += __shfl_xor_sync(0xffffffffu, sum0, 1);
            sum0 += __shfl_xor_sync(0xffffffffu, sum0, 2);
            sum1 += __shfl_xor_sync(0xffffffffu, sum1, 1);
            sum1 += __shfl_xor_sync(0xffffffffu, sum1, 2);
            l0 = l0 * corr0 + sum0;
            l1 = l1 * corr1 + sum1;

            #pragma unroll
            for (int sf = 0; sf < 8; sf++) {
                O[sf][0] *= corr0; O[sf][1] *= corr0;
                O[sf][2] *= corr1; O[sf][3] *= corr1;
            }

            uint32_t pa[4][4], pl[4][4];
            #pragma unroll
            for (int j = 0; j < 4; j++) {
                #pragma unroll
                for (int q = 0; q < 4; q++) {
                    const int sf = 2 * j + (q >> 1);
                    const int e  = (q & 1) * 2;
                    const float a = S[sf][e], c = S[sf][e + 1];
                    const uint32_t ph = packh2(a, c);
                    pa[j][q] = ph;
                    const float2 fb = __half22float2(*(const __half2*)&ph);
                    pl[j][q] = packh2(a - fb.x, c - fb.y);
                }
            }

            const uint32_t vbase = smb + SV0 + (uint32_t)(bufi * (64 * AST)) + vlane;
            #pragma unroll
            for (int dd = 0; dd < 4; dd++)
                #pragma unroll
                for (int j = 0; j < 4; j++) {
                    uint32_t vf[4];
                    ldsm4t(vf, vbase + (uint32_t)(j * 16 * AST + dd * 32));
                    mma16816h(O[2*dd],   pa[j], vf[0], vf[1]);
                    mma16816h(O[2*dd+1], pa[j], vf[2], vf[3]);
                    mma16816h(O[2*dd],   pl[j], vf[0], vf[1]);
                    mma16816h(O[2*dd+1], pl[j], vf[2], vf[3]);
                }
        }
        __syncthreads();
    }

    // ---- epilogue: normalize, split to fp16 hi/lo, store into g_ah/g_al ----
    const float inv0 = 1.f / l0, inv1 = 1.f / l1;
    const int row0 = qb + wid * 16 + (lane >> 2);
    #pragma unroll
    for (int sf = 0; sf < 8; sf++) {
        const int col = h * DD + sf * 8 + (lane & 3) * 2;
        const size_t p0 = (size_t)(b * TT + row0) * CC + col;
        const size_t p1 = (size_t)(b * TT + row0 + 8) * CC + col;
        float o00 = O[sf][0] * inv0, o01 = O[sf][1] * inv0;
        float o10 = O[sf][2] * inv1, o11 = O[sf][3] * inv1;
        __half2 h0 = __floats2half2_rn(o00, o01);
        __half2 h1 = __floats2half2_rn(o10, o11);
        *(__half2*)(g_ah + p0) = h0;
        *(__half2*)(g_ah + p1) = h1;
        float2 f0 = __half22float2(h0), f1 = __half22float2(h1);
        *(__half2*)(g_al + p0) = __floats2half2_rn(o00 - f0.x, o01 - f0.y);
        *(__half2*)(g_al + p1) = __floats2half2_rn(o10 - f1.x, o11 - f1.y);
    }
}

// ---------------------------------------------------------------------------
// Launch sequence
// ---------------------------------------------------------------------------
extern "C" void kernel_launch(void* const* d_in, const int* in_sizes, int n_in,
                              void* d_out, int out_size)
{
    const float* x  = (const float*)d_in[0];
    const float* Wq = (const float*)d_in[1];
    const float* bq = (const float*)d_in[2];
    const float* Wk = (const float*)d_in[3];
    const float* bk = (const float*)d_in[4];
    const float* Wv = (const float*)d_in[5];
    const float* bv = (const float*)d_in[6];
    const float* Wo = (const float*)d_in[7];
    const float* bo = (const float*)d_in[8];
    float* out = (float*)d_out;

    cudaFuncSetAttribute(gemm_fp16<true>,  cudaFuncAttributeMaxDynamicSharedMemorySize, GSMEM_TOTAL);
    cudaFuncSetAttribute(gemm_fp16<false>, cudaFuncAttributeMaxDynamicSharedMemorySize, GSMEM_TOTAL);
    cudaFuncSetAttribute(attn_tc,          cudaFuncAttributeMaxDynamicSharedMemorySize, ASMEM);

    const dim3 gcv(MM * CC / 4 / 256);
    const dim3 gtr(CC / 32, CC / 32, 4);
    const dim3 gqkv(CC / BN, MM / BM, 3);
    const dim3 go(CC / BN, MM / BM);

    cvt_split_x<<<gcv, 256>>>(x);
    cvt_wt_all<<<gtr, 256>>>(Wq, Wk, Wv, Wo);

    gemm_fp16<true><<<gqkv, 256, GSMEM_TOTAL>>>(bq, bk, bv, nullptr);

    const dim3 ga(TT / AQ, HH, BB);
    attn_tc<<<ga, 256, ASMEM>>>();

    gemm_fp16<false><<<go, 256, GSMEM_TOTAL>>>(bo, nullptr, nullptr, out);
}

// round 7
// speedup vs baseline: 7.2413x; 1.4184x over previous
#include <cuda_runtime.h>
#include <cuda_fp16.h>
#include <cstdint>

#define BB 2
#define TT 2048
#define CC 1024
#define HH 16
#define DD 64
#define MM (BB*TT)

// ---- projection GEMM tiling ----
#define BM 128
#define BN 128
#define BK 32
#define PADK 40                 // smem row stride in halves (80 B)
#define ROWB (PADK*2)
#define AH_OFF 0
#define BH_OFF 10240
#define STAGE4 20480
#define GSMEM_TOTAL (4*STAGE4)  // 81920 B

// ---- attention tiling ----
#define AQ  128
#define AKV 64
#define AST 144
#define SQH 0
#define SK0 (128*AST)           // 18432
#define SV0 (SK0 + 2*64*AST)    // 36864
#define ASMEM (SV0 + 2*64*AST)  // 55296

#define SCQ (0.125f * 1.44269504088896340736f)   // 1/sqrt(D) * log2(e)

// ---------------------------------------------------------------------------
// Scratch (allocation-free device globals) — all fp16
// ---------------------------------------------------------------------------
__device__ __align__(256) __half g_qh[MM*CC];    // Q * 0.125*log2e
__device__ __align__(256) __half g_kh[MM*CC];
__device__ __align__(256) __half g_vh[MM*CC];
__device__ __align__(256) __half g_ah[MM*CC];    // A operand (x, later att out)
__device__ __align__(256) __half g_wh[4][CC*CC]; // W transposed [n][k], fp16

// ---------------------------------------------------------------------------
// PTX helpers (baseline sm_80+ features only)
// ---------------------------------------------------------------------------
__device__ __forceinline__ uint32_t smem_u32(const void* p) {
    uint32_t a;
    asm("{ .reg .u64 t; cvta.to.shared.u64 t, %1; cvt.u32.u64 %0, t; }" : "=r"(a) : "l"(p));
    return a;
}
__device__ __forceinline__ void cpa16(uint32_t dst, const void* src) {
    asm volatile("cp.async.cg.shared.global [%0], [%1], 16;" :: "r"(dst), "l"(src));
}
__device__ __forceinline__ void cpa_commit() {
    asm volatile("cp.async.commit_group;" ::: "memory");
}
template<int N>
__device__ __forceinline__ void cpa_wait() {
    asm volatile("cp.async.wait_group %0;" :: "n"(N) : "memory");
}
__device__ __forceinline__ void ldsm4(uint32_t* r, uint32_t addr) {
    asm volatile("ldmatrix.sync.aligned.m8n8.x4.shared.b16 {%0,%1,%2,%3}, [%4];"
        : "=r"(r[0]), "=r"(r[1]), "=r"(r[2]), "=r"(r[3]) : "r"(addr));
}
__device__ __forceinline__ void ldsm4t(uint32_t* r, uint32_t addr) {
    asm volatile("ldmatrix.sync.aligned.m8n8.x4.trans.shared.b16 {%0,%1,%2,%3}, [%4];"
        : "=r"(r[0]), "=r"(r[1]), "=r"(r[2]), "=r"(r[3]) : "r"(addr));
}
__device__ __forceinline__ void mma16816h(float* c, const uint32_t* a,
                                          uint32_t b0, uint32_t b1) {
    asm volatile("mma.sync.aligned.m16n8k16.row.col.f32.f16.f16.f32 "
        "{%0,%1,%2,%3}, {%4,%5,%6,%7}, {%8,%9}, {%0,%1,%2,%3};"
        : "+f"(c[0]), "+f"(c[1]), "+f"(c[2]), "+f"(c[3])
        : "r"(a[0]), "r"(a[1]), "r"(a[2]), "r"(a[3]), "r"(b0), "r"(b1));
}
__device__ __forceinline__ float ex2f(float x) {
    float r;
    asm("ex2.approx.ftz.f32 %0, %1;" : "=f"(r) : "f"(x));
    return r;
}
__device__ __forceinline__ uint32_t packh2(float a, float b) {
    __half2 h = __floats2half2_rn(a, b);
    return *(uint32_t*)&h;
}

// ---------------------------------------------------------------------------
// Convert x: fp32 -> fp16 into g_ah.
// ---------------------------------------------------------------------------
__global__ void __launch_bounds__(256) cvt_x(const float* __restrict__ in)
{
    size_t i = (size_t)blockIdx.x * 256 + threadIdx.x;   // float4 index
    float4 v = ((const float4*)in)[i];
    uint2 uh;
    __half2 h0 = __floats2half2_rn(v.x, v.y);
    __half2 h1 = __floats2half2_rn(v.z, v.w);
    uh.x = *(uint32_t*)&h0;
    uh.y = *(uint32_t*)&h1;
    ((uint2*)g_ah)[i] = uh;
}

// ---------------------------------------------------------------------------
// Transpose-convert all 4 weights: W[k][n] fp32 -> g_wh[z][n][k] fp16.
// ---------------------------------------------------------------------------
__global__ void __launch_bounds__(256) cvt_wt_all(const float* __restrict__ W0,
                                                  const float* __restrict__ W1,
                                                  const float* __restrict__ W2,
                                                  const float* __restrict__ W3)
{
    const float* Ws[4] = {W0, W1, W2, W3};
    const float* W = Ws[blockIdx.z];
    __half* dst = g_wh[blockIdx.z];
    __shared__ float t[32][33];
    const int n0 = blockIdx.x * 32, k0 = blockIdx.y * 32;
    const int tx = threadIdx.x & 31, ty = threadIdx.x >> 5;
    #pragma unroll
    for (int i = 0; i < 4; i++)
        t[ty + 8*i][tx] = W[(size_t)(k0 + ty + 8*i) * CC + n0 + tx];
    __syncthreads();
    #pragma unroll
    for (int i = 0; i < 4; i++) {
        int nn = ty + 8*i;
        dst[(size_t)(n0 + nn) * CC + k0 + tx] = __float2half(t[tx][nn]);
    }
}

// ---------------------------------------------------------------------------
// fp16 HGEMM:  Y[128x128 tile] = A @ Wh^T + bias   (single-term A and W)
// QKV=true: grid.z selects q/k/v; QKV=false: O-projection, fp32 to Yext.
// 256 threads = 8 warps (2m x 4n), warp tile 64x32, 4-stage cp.async pipeline.
// ---------------------------------------------------------------------------
template<bool QKV>
__global__ void __launch_bounds__(256) gemm_fp16(const float* __restrict__ bias0,
                                                 const float* __restrict__ bias1,
                                                 const float* __restrict__ bias2,
                                                 float* __restrict__ Yext)
{
    extern __shared__ char sm[];
    const uint32_t smb = smem_u32(sm);
    const int tid  = threadIdx.x;
    const int wid  = tid >> 5;
    const int lane = tid & 31;
    const int warpM = wid >> 2;
    const int warpN = wid & 3;
    const int z = QKV ? (int)blockIdx.z : 3;

    const __half* __restrict__ Ah = g_ah;
    const __half* __restrict__ Bh = g_wh[z];
    const float* bias = QKV ? (z == 0 ? bias0 : z == 1 ? bias1 : bias2) : bias0;

    const int rowBase = blockIdx.y * BM;
    const int colBase = blockIdx.x * BN;

    const uint32_t aLane = (uint32_t)((lane & 15) * PADK + (lane >> 4) * 8) * 2;
    const uint32_t bLane = (uint32_t)(((lane & 7) + ((lane >> 4) & 1) * 8) * PADK
                                      + ((lane >> 3) & 1) * 8) * 2;

    float acc[4][4][4];
    #pragma unroll
    for (int i = 0; i < 4; i++)
        #pragma unroll
        for (int j = 0; j < 4; j++)
            #pragma unroll
            for (int r = 0; r < 4; r++) acc[i][j][r] = 0.f;

    auto stage_load = [&](int s, int buf) {
        const int kb = s * BK;
        const uint32_t base = smb + buf * STAGE4;
        #pragma unroll
        for (int i = 0; i < 2; i++) {
            const int idx = tid + i * 256;
            const int row = idx >> 2, ch = idx & 3;
            const uint32_t d = base + (uint32_t)(row * ROWB + ch * 16);
            cpa16(d + AH_OFF, (const char*)(Ah + (size_t)(rowBase + row) * CC + kb) + ch * 16);
            cpa16(d + BH_OFF, (const char*)(Bh + (size_t)(colBase + row) * CC + kb) + ch * 16);
        }
    };

    const int NSTAGE = CC / BK;       // 32
    stage_load(0, 0); cpa_commit();
    stage_load(1, 1); cpa_commit();
    stage_load(2, 2); cpa_commit();

    int buf = 0;
    for (int kt = 0; kt < NSTAGE; kt++) {
        if (kt + 3 < NSTAGE) {
            stage_load(kt + 3, (buf + 3) & 3);
            cpa_commit();
            cpa_wait<3>();
        } else if (kt + 2 < NSTAGE) {
            cpa_wait<2>();
        } else if (kt + 1 < NSTAGE) {
            cpa_wait<1>();
        } else {
            cpa_wait<0>();
        }
        __syncthreads();

        const uint32_t aBase = smb + buf * STAGE4 + AH_OFF
                             + (uint32_t)(warpM * 64 * ROWB) + aLane;
        const uint32_t bBase = smb + buf * STAGE4 + BH_OFF
                             + (uint32_t)(warpN * 32 * ROWB) + bLane;

        #pragma unroll
        for (int kk = 0; kk < BK; kk += 16) {
            uint32_t ah[4][4], bh[2][4];
            #pragma unroll
            for (int mt = 0; mt < 4; mt++)
                ldsm4(ah[mt], aBase + (uint32_t)(mt * 16 * ROWB + kk * 2));
            #pragma unroll
            for (int np = 0; np < 2; np++)
                ldsm4(bh[np], bBase + (uint32_t)(np * 16 * ROWB + kk * 2));
            #pragma unroll
            for (int mt = 0; mt < 4; mt++)
                #pragma unroll
                for (int nt = 0; nt < 4; nt++) {
                    const int np = nt >> 1, s2 = (nt & 1) * 2;
                    mma16816h(acc[mt][nt], ah[mt], bh[np][s2], bh[np][s2 + 1]);
                }
        }
        __syncthreads();
        buf = (buf + 1) & 3;
    }

    #pragma unroll
    for (int mt = 0; mt < 4; mt++) {
        const int row = rowBase + warpM * 64 + mt * 16 + (lane >> 2);
        #pragma unroll
        for (int nt = 0; nt < 4; nt++) {
            const int col = colBase + warpN * 32 + nt * 8 + (lane & 3) * 2;
            const float2 b2 = *(const float2*)(bias + col);
            float v00 = acc[mt][nt][0] + b2.x, v01 = acc[mt][nt][1] + b2.y;
            float v10 = acc[mt][nt][2] + b2.x, v11 = acc[mt][nt][3] + b2.y;
            if constexpr (!QKV) {
                float2 o0 = {v00, v01}, o1 = {v10, v11};
                *(float2*)(Yext + (size_t)row * CC + col)       = o0;
                *(float2*)(Yext + (size_t)(row + 8) * CC + col) = o1;
            } else {
                __half* dst = (z == 0) ? g_qh : (z == 1) ? g_kh : g_vh;
                if (z == 0) { v00 *= SCQ; v01 *= SCQ; v10 *= SCQ; v11 *= SCQ; }
                *(__half2*)(dst + (size_t)row * CC + col)       = __floats2half2_rn(v00, v01);
                *(__half2*)(dst + (size_t)(row + 8) * CC + col) = __floats2half2_rn(v10, v11);
            }
        }
    }
}

// ---------------------------------------------------------------------------
// Tensor-core causal flash attention (fp16 mma; Q single-term scores,
// P split 2-term PV).  Epilogue writes fp16 directly into g_ah
// (A-operand of the output projection).  2 CTAs/SM.
// ---------------------------------------------------------------------------
__global__ void __launch_bounds__(256, 2) attn_tc()
{
    extern __shared__ char sm[];
    const uint32_t smb = smem_u32(sm);
    const int tid = threadIdx.x, wid = tid >> 5, lane = tid & 31;
    const int qb = (int)(gridDim.x - 1 - blockIdx.x) * AQ;   // heavy CTAs first
    const int h = blockIdx.y, b = blockIdx.z;
    const size_t rowOff = (size_t)(b * TT) * CC + h * DD;

    // ---- load Q tile + KV tile 0 via cp.async ----
    #pragma unroll
    for (int i = 0; i < 4; i++) {
        int idx = tid + i * 256;                 // 0..1023
        int r = idx >> 3, ch = idx & 7;
        cpa16(smb + SQH + (uint32_t)(r * AST + ch * 16),
              g_qh + rowOff + (size_t)(qb + r) * CC + ch * 8);
    }
    auto stageKV = [&](int t, int bufi) {
        int kb = t * AKV;
        #pragma unroll
        for (int i = 0; i < 4; i++) {
            int idx = tid + i * 256;
            int mv = idx >> 9, r = (idx >> 3) & 63, ch = idx & 7;
            const __half* src = (mv ? g_vh : g_kh) + rowOff + (size_t)(kb + r) * CC + ch * 8;
            cpa16(smb + (mv ? SV0 : SK0) + (uint32_t)(bufi * (64 * AST) + r * AST + ch * 16), src);
        }
    };
    stageKV(0, 0);
    cpa_commit();
    cpa_wait<0>();
    __syncthreads();

    // ---- Q fragments (register resident) ----
    const uint32_t qlane = (uint32_t)((lane & 15) * AST + (lane >> 4) * 16);
    uint32_t qf[4][4];
    {
        const uint32_t qbase = smb + SQH + (uint32_t)(wid * 16 * AST) + qlane;
        #pragma unroll
        for (int ks = 0; ks < 4; ks++)
            ldsm4(qf[ks], qbase + ks * 32);
    }

    float O[8][4];
    #pragma unroll
    for (int i = 0; i < 8; i++)
        #pragma unroll
        for (int j = 0; j < 4; j++) O[i][j] = 0.f;
    float m0 = -1e30f, m1 = -1e30f, l0 = 0.f, l1 = 0.f;

    const int wr0 = qb + wid * 16;
    const int ntiles = qb / AKV + 2;
    const uint32_t klane = (uint32_t)(((lane & 7) + ((lane >> 4) & 1) * 8) * AST
                                      + ((lane >> 3) & 1) * 16);
    const uint32_t vlane = (uint32_t)(((lane & 7) + ((lane >> 3) & 1) * 8) * AST
                                      + ((lane >> 4) & 1) * 16);

    for (int t = 0; t < ntiles; t++) {
        const int bufi = t & 1;
        if (t + 1 < ntiles) {
            stageKV(t + 1, bufi ^ 1);
            cpa_commit();
            cpa_wait<1>();
        } else {
            cpa_wait<0>();
        }
        __syncthreads();

        const int kb = t * AKV;
        if (kb <= wr0 + 15) {
            // ---- scores S = Q . K^T (single term) ----
            float S[8][4];
            #pragma unroll
            for (int i = 0; i < 8; i++)
                #pragma unroll
                for (int j = 0; j < 4; j++) S[i][j] = 0.f;

            const uint32_t kbase = smb + SK0 + (uint32_t)(bufi * (64 * AST)) + klane;
            #pragma unroll
            for (int nn = 0; nn < 4; nn++)
                #pragma unroll
                for (int ks = 0; ks < 4; ks++) {
                    uint32_t kf[4];
                    ldsm4(kf, kbase + (uint32_t)(nn * 16 * AST + ks * 32));
                    mma16816h(S[2*nn],   qf[ks], kf[0], kf[1]);
                    mma16816h(S[2*nn+1], qf[ks], kf[2], kf[3]);
                }

            // ---- causal mask ----
            if (kb + 63 > wr0) {
                const int r0 = wr0 + (lane >> 2), r1 = r0 + 8;
                #pragma unroll
                for (int sf = 0; sf < 8; sf++) {
                    const int c = kb + sf * 8 + (lane & 3) * 2;
                    if (c     > r0) S[sf][0] = -1e30f;
                    if (c + 1 > r0) S[sf][1] = -1e30f;
                    if (c     > r1) S[sf][2] = -1e30f;
                    if (c + 1 > r1) S[sf][3] = -1e30f;
                }
            }

            // ---- online softmax (log2 domain) ----
            float mx0 = -1e30f, mx1 = -1e30f;
            #pragma unroll
            for (int sf = 0; sf < 8; sf++) {
                mx0 = fmaxf(mx0, fmaxf(S[sf][0], S[sf][1]));
                mx1 = fmaxf(mx1, fmaxf(S[sf][2], S[sf][3]));
            }
            mx0 = fmaxf(mx0, __shfl_xor_sync(0xffffffffu, mx0, 1));
            mx0 = fmaxf(mx0, __shfl_xor_sync(0xffffffffu, mx0, 2));
            mx1 = fmaxf(mx1, __shfl_xor_sync(0xffffffffu, mx1, 1));
            mx1 = fmaxf(mx1, __shfl_xor_sync(0xffffffffu, mx1, 2));
            const float nm0 = fmaxf(m0, mx0), nm1 = fmaxf(m1, mx1);
            const float corr0 = ex2f(m0 - nm0), corr1 = ex2f(m1 - nm1);
            m0 = nm0; m1 = nm1;

            float sum0 = 0.f, sum1 = 0.f;
            #pragma unroll
            for (int sf = 0; sf < 8; sf++) {
                S[sf][0] = ex2f(S[sf][0] - nm0);
                S[sf][1] = ex2f(S[sf][1] - nm0);
                S[sf][2] = ex2f(S[sf][2] - nm1);
                S[sf][3] = ex2f(S[sf][3] - nm1);
                sum0 += S[sf][0] + S[sf][1];
                sum1 += S[sf][2] + S[sf][3];
            }
            sum0 += __shfl_xor_sync(0xffffffffu, sum0, 1);
            sum0 += __shfl_xor_sync(0xffffffffu, sum0, 2);
            sum1 += __shfl_xor_sync(0xffffffffu, sum1, 1);
            sum1 += __shfl_xor_sync(0xffffffffu, sum1, 2);
            l0 = l0 * corr0 + sum0;
            l1 = l1 * corr1 + sum1;

            #pragma unroll
            for (int sf = 0; sf < 8; sf++) {
                O[sf][0] *= corr0; O[sf][1] *= corr0;
                O[sf][2] *= corr1; O[sf][3] *= corr1;
            }

            // ---- pack P into fp16 A-fragments (hi + lo) ----
            uint32_t pa[4][4], pl[4][4];
            #pragma unroll
            for (int j = 0; j < 4; j++) {
                #pragma unroll
                for (int q = 0; q < 4; q++) {
                    const int sf = 2 * j + (q >> 1);
                    const int e  = (q & 1) * 2;
                    const float a = S[sf][e], c = S[sf][e + 1];
                    const uint32_t ph = packh2(a, c);
                    pa[j][q] = ph;
                    const float2 fb = __half22float2(*(const __half2*)&ph);
                    pl[j][q] = packh2(a - fb.x, c - fb.y);
                }
            }

            // ---- O += (Ph+Pl) . V ----
            const uint32_t vbase = smb + SV0 + (uint32_t)(bufi * (64 * AST)) + vlane;
            #pragma unroll
            for (int dd = 0; dd < 4; dd++)
                #pragma unroll
                for (int j = 0; j < 4; j++) {
                    uint32_t vf[4];
                    ldsm4t(vf, vbase + (uint32_t)(j * 16 * AST + dd * 32));
                    mma16816h(O[2*dd],   pa[j], vf[0], vf[1]);
                    mma16816h(O[2*dd+1], pa[j], vf[2], vf[3]);
                    mma16816h(O[2*dd],   pl[j], vf[0], vf[1]);
                    mma16816h(O[2*dd+1], pl[j], vf[2], vf[3]);
                }
        }
        __syncthreads();
    }

    // ---- epilogue: normalize, convert fp16, store into g_ah ----
    const float inv0 = 1.f / l0, inv1 = 1.f / l1;
    const int row0 = qb + wid * 16 + (lane >> 2);
    #pragma unroll
    for (int sf = 0; sf < 8; sf++) {
        const int col = h * DD + sf * 8 + (lane & 3) * 2;
        *(__half2*)(g_ah + (size_t)(b * TT + row0) * CC + col) =
            __floats2half2_rn(O[sf][0] * inv0, O[sf][1] * inv0);
        *(__half2*)(g_ah + (size_t)(b * TT + row0 + 8) * CC + col) =
            __floats2half2_rn(O[sf][2] * inv1, O[sf][3] * inv1);
    }
}

// ---------------------------------------------------------------------------
// Launch sequence
// ---------------------------------------------------------------------------
extern "C" void kernel_launch(void* const* d_in, const int* in_sizes, int n_in,
                              void* d_out, int out_size)
{
    const float* x  = (const float*)d_in[0];
    const float* Wq = (const float*)d_in[1];
    const float* bq = (const float*)d_in[2];
    const float* Wk = (const float*)d_in[3];
    const float* bk = (const float*)d_in[4];
    const float* Wv = (const float*)d_in[5];
    const float* bv = (const float*)d_in[6];
    const float* Wo = (const float*)d_in[7];
    const float* bo = (const float*)d_in[8];
    float* out = (float*)d_out;

    cudaFuncSetAttribute(gemm_fp16<true>,  cudaFuncAttributeMaxDynamicSharedMemorySize, GSMEM_TOTAL);
    cudaFuncSetAttribute(gemm_fp16<false>, cudaFuncAttributeMaxDynamicSharedMemorySize, GSMEM_TOTAL);
    cudaFuncSetAttribute(attn_tc,          cudaFuncAttributeMaxDynamicSharedMemorySize, ASMEM);

    const dim3 gcv(MM * CC / 4 / 256);
    const dim3 gtr(CC / 32, CC / 32, 4);
    const dim3 gqkv(CC / BN, MM / BM, 3);
    const dim3 go(CC / BN, MM / BM);

    cvt_x<<<gcv, 256>>>(x);
    cvt_wt_all<<<gtr, 256>>>(Wq, Wk, Wv, Wo);

    gemm_fp16<true><<<gqkv, 256, GSMEM_TOTAL>>>(bq, bk, bv, nullptr);

    const dim3 ga(TT / AQ, HH, BB);
    attn_tc<<<ga, 256, ASMEM>>>();

    gemm_fp16<false><<<go, 256, GSMEM_TOTAL>>>(bo, nullptr, nullptr, out);
}

// round 8
// speedup vs baseline: 8.9676x; 1.2384x over previous
#include <cuda_runtime.h>
#include <cuda_fp16.h>
#include <cstdint>

#define BB 2
#define TT 2048
#define CC 1024
#define HH 16
#define DD 64
#define MM (BB*TT)

// ---- projection GEMM tiling ----
#define BM 128
#define BN 128
#define BK 64
#define PADK 72                 // smem row stride in halves (144 B), conflict-free
#define ROWB (PADK*2)           // 144 bytes
#define AH_OFF 0
#define BH_OFF (128*ROWB)       // 18432
#define STAGEB (2*128*ROWB)     // 36864
#define GSMEM_TOTAL (3*STAGEB)  // 110592 B

// ---- attention tiling ----
#define AQ  128
#define AKV 64
#define AST 144
#define SQH 0
#define SK0 (128*AST)           // 18432
#define SV0 (SK0 + 2*64*AST)    // 36864
#define ASMEM (SV0 + 2*64*AST)  // 55296

#define SCQ (0.125f * 1.44269504088896340736f)   // 1/sqrt(D) * log2(e)

// ---------------------------------------------------------------------------
// Scratch (allocation-free device globals) — all fp16
// ---------------------------------------------------------------------------
__device__ __align__(256) __half g_qh[MM*CC];    // Q * 0.125*log2e
__device__ __align__(256) __half g_kh[MM*CC];
__device__ __align__(256) __half g_vh[MM*CC];
__device__ __align__(256) __half g_ah[MM*CC];    // A operand (x, later att out)
__device__ __align__(256) __half g_wh[4][CC*CC]; // W transposed [n][k], fp16

// ---------------------------------------------------------------------------
// PTX helpers (baseline sm_80+ features only)
// ---------------------------------------------------------------------------
__device__ __forceinline__ uint32_t smem_u32(const void* p) {
    uint32_t a;
    asm("{ .reg .u64 t; cvta.to.shared.u64 t, %1; cvt.u32.u64 %0, t; }" : "=r"(a) : "l"(p));
    return a;
}
__device__ __forceinline__ void cpa16(uint32_t dst, const void* src) {
    asm volatile("cp.async.cg.shared.global [%0], [%1], 16;" :: "r"(dst), "l"(src));
}
__device__ __forceinline__ void cpa_commit() {
    asm volatile("cp.async.commit_group;" ::: "memory");
}
template<int N>
__device__ __forceinline__ void cpa_wait() {
    asm volatile("cp.async.wait_group %0;" :: "n"(N) : "memory");
}
__device__ __forceinline__ void ldsm4(uint32_t* r, uint32_t addr) {
    asm volatile("ldmatrix.sync.aligned.m8n8.x4.shared.b16 {%0,%1,%2,%3}, [%4];"
        : "=r"(r[0]), "=r"(r[1]), "=r"(r[2]), "=r"(r[3]) : "r"(addr));
}
__device__ __forceinline__ void ldsm4t(uint32_t* r, uint32_t addr) {
    asm volatile("ldmatrix.sync.aligned.m8n8.x4.trans.shared.b16 {%0,%1,%2,%3}, [%4];"
        : "=r"(r[0]), "=r"(r[1]), "=r"(r[2]), "=r"(r[3]) : "r"(addr));
}
__device__ __forceinline__ void mma16816h(float* c, const uint32_t* a,
                                          uint32_t b0, uint32_t b1) {
    asm volatile("mma.sync.aligned.m16n8k16.row.col.f32.f16.f16.f32 "
        "{%0,%1,%2,%3}, {%4,%5,%6,%7}, {%8,%9}, {%0,%1,%2,%3};"
        : "+f"(c[0]), "+f"(c[1]), "+f"(c[2]), "+f"(c[3])
        : "r"(a[0]), "r"(a[1]), "r"(a[2]), "r"(a[3]), "r"(b0), "r"(b1));
}
__device__ __forceinline__ float ex2f(float x) {
    float r;
    asm("ex2.approx.ftz.f32 %0, %1;" : "=f"(r) : "f"(x));
    return r;
}
__device__ __forceinline__ uint32_t packh2(float a, float b) {
    __half2 h = __floats2half2_rn(a, b);
    return *(uint32_t*)&h;
}

// ---------------------------------------------------------------------------
// Convert x: fp32 -> fp16 into g_ah.
// ---------------------------------------------------------------------------
__global__ void __launch_bounds__(256) cvt_x(const float* __restrict__ in)
{
    size_t i = (size_t)blockIdx.x * 256 + threadIdx.x;   // float4 index
    float4 v = ((const float4*)in)[i];
    uint2 uh;
    __half2 h0 = __floats2half2_rn(v.x, v.y);
    __half2 h1 = __floats2half2_rn(v.z, v.w);
    uh.x = *(uint32_t*)&h0;
    uh.y = *(uint32_t*)&h1;
    ((uint2*)g_ah)[i] = uh;
}

// ---------------------------------------------------------------------------
// Transpose-convert all 4 weights: W[k][n] fp32 -> g_wh[z][n][k] fp16.
// ---------------------------------------------------------------------------
__global__ void __launch_bounds__(256) cvt_wt_all(const float* __restrict__ W0,
                                                  const float* __restrict__ W1,
                                                  const float* __restrict__ W2,
                                                  const float* __restrict__ W3)
{
    const float* Ws[4] = {W0, W1, W2, W3};
    const float* W = Ws[blockIdx.z];
    __half* dst = g_wh[blockIdx.z];
    __shared__ float t[32][33];
    const int n0 = blockIdx.x * 32, k0 = blockIdx.y * 32;
    const int tx = threadIdx.x & 31, ty = threadIdx.x >> 5;
    #pragma unroll
    for (int i = 0; i < 4; i++)
        t[ty + 8*i][tx] = W[(size_t)(k0 + ty + 8*i) * CC + n0 + tx];
    __syncthreads();
    #pragma unroll
    for (int i = 0; i < 4; i++) {
        int nn = ty + 8*i;
        dst[(size_t)(n0 + nn) * CC + k0 + tx] = __float2half(t[tx][nn]);
    }
}

// ---------------------------------------------------------------------------
// fp16 HGEMM:  Y[128x128 tile] = A @ Wh^T + bias
// BK=64 stages (half the syncs of BK=32), 3-stage cp.async pipeline.
// 256 threads = 8 warps (2m x 4n), warp tile 64x32.
// ---------------------------------------------------------------------------
template<bool QKV>
__global__ void __launch_bounds__(256) gemm_fp16(const float* __restrict__ bias0,
                                                 const float* __restrict__ bias1,
                                                 const float* __restrict__ bias2,
                                                 float* __restrict__ Yext)
{
    extern __shared__ char sm[];
    const uint32_t smb = smem_u32(sm);
    const int tid  = threadIdx.x;
    const int wid  = tid >> 5;
    const int lane = tid & 31;
    const int warpM = wid >> 2;
    const int warpN = wid & 3;
    const int z = QKV ? (int)blockIdx.z : 3;

    const __half* __restrict__ Ah = g_ah;
    const __half* __restrict__ Bh = g_wh[z];
    const float* bias = QKV ? (z == 0 ? bias0 : z == 1 ? bias1 : bias2) : bias0;

    const int rowBase = blockIdx.y * BM;
    const int colBase = blockIdx.x * BN;

    const uint32_t aLane = (uint32_t)((lane & 15) * PADK + (lane >> 4) * 8) * 2;
    const uint32_t bLane = (uint32_t)(((lane & 7) + ((lane >> 4) & 1) * 8) * PADK
                                      + ((lane >> 3) & 1) * 8) * 2;

    float acc[4][4][4];
    #pragma unroll
    for (int i = 0; i < 4; i++)
        #pragma unroll
        for (int j = 0; j < 4; j++)
            #pragma unroll
            for (int r = 0; r < 4; r++) acc[i][j][r] = 0.f;

    // per stage: 128 rows x 8 chunks(16B) x 2 matrices = 2048 cp.async / 256 thr
    auto stage_load = [&](int s, int buf) {
        const int kb = s * BK;
        const uint32_t base = smb + buf * STAGEB;
        #pragma unroll
        for (int i = 0; i < 4; i++) {
            const int idx = tid + i * 256;       // 0..1023
            const int row = idx >> 3, ch = idx & 7;
            const uint32_t d = base + (uint32_t)(row * ROWB + ch * 16);
            cpa16(d + AH_OFF, (const char*)(Ah + (size_t)(rowBase + row) * CC + kb) + ch * 16);
            cpa16(d + BH_OFF, (const char*)(Bh + (size_t)(colBase + row) * CC + kb) + ch * 16);
        }
    };

    const int NSTAGE = CC / BK;       // 16
    stage_load(0, 0); cpa_commit();
    stage_load(1, 1); cpa_commit();

    int buf = 0;
    for (int kt = 0; kt < NSTAGE; kt++) {
        if (kt + 2 < NSTAGE) {
            int nb = buf + 2; if (nb >= 3) nb -= 3;
            stage_load(kt + 2, nb);
            cpa_commit();
            cpa_wait<2>();
        } else if (kt + 1 < NSTAGE) {
            cpa_wait<1>();
        } else {
            cpa_wait<0>();
        }
        __syncthreads();

        const uint32_t aBase = smb + buf * STAGEB + AH_OFF
                             + (uint32_t)(warpM * 64 * ROWB) + aLane;
        const uint32_t bBase = smb + buf * STAGEB + BH_OFF
                             + (uint32_t)(warpN * 32 * ROWB) + bLane;

        #pragma unroll
        for (int kk = 0; kk < BK; kk += 16) {
            uint32_t ah[4][4], bh[2][4];
            #pragma unroll
            for (int mt = 0; mt < 4; mt++)
                ldsm4(ah[mt], aBase + (uint32_t)(mt * 16 * ROWB + kk * 2));
            #pragma unroll
            for (int np = 0; np < 2; np++)
                ldsm4(bh[np], bBase + (uint32_t)(np * 16 * ROWB + kk * 2));
            #pragma unroll
            for (int mt = 0; mt < 4; mt++)
                #pragma unroll
                for (int nt = 0; nt < 4; nt++) {
                    const int np = nt >> 1, s2 = (nt & 1) * 2;
                    mma16816h(acc[mt][nt], ah[mt], bh[np][s2], bh[np][s2 + 1]);
                }
        }
        __syncthreads();
        buf++; if (buf == 3) buf = 0;
    }

    #pragma unroll
    for (int mt = 0; mt < 4; mt++) {
        const int row = rowBase + warpM * 64 + mt * 16 + (lane >> 2);
        #pragma unroll
        for (int nt = 0; nt < 4; nt++) {
            const int col = colBase + warpN * 32 + nt * 8 + (lane & 3) * 2;
            const float2 b2 = *(const float2*)(bias + col);
            float v00 = acc[mt][nt][0] + b2.x, v01 = acc[mt][nt][1] + b2.y;
            float v10 = acc[mt][nt][2] + b2.x, v11 = acc[mt][nt][3] + b2.y;
            if constexpr (!QKV) {
                float2 o0 = {v00, v01}, o1 = {v10, v11};
                *(float2*)(Yext + (size_t)row * CC + col)       = o0;
                *(float2*)(Yext + (size_t)(row + 8) * CC + col) = o1;
            } else {
                __half* dst = (z == 0) ? g_qh : (z == 1) ? g_kh : g_vh;
                if (z == 0) { v00 *= SCQ; v01 *= SCQ; v10 *= SCQ; v11 *= SCQ; }
                *(__half2*)(dst + (size_t)row * CC + col)       = __floats2half2_rn(v00, v01);
                *(__half2*)(dst + (size_t)(row + 8) * CC + col) = __floats2half2_rn(v10, v11);
            }
        }
    }
}

// ---------------------------------------------------------------------------
// Tensor-core causal flash attention (fp16 mma; Q single-term scores,
// P single-term PV).  Epilogue writes fp16 directly into g_ah.  2 CTAs/SM.
// ---------------------------------------------------------------------------
__global__ void __launch_bounds__(256, 2) attn_tc()
{
    extern __shared__ char sm[];
    const uint32_t smb = smem_u32(sm);
    const int tid = threadIdx.x, wid = tid >> 5, lane = tid & 31;
    const int qb = (int)(gridDim.x - 1 - blockIdx.x) * AQ;   // heavy CTAs first
    const int h = blockIdx.y, b = blockIdx.z;
    const size_t rowOff = (size_t)(b * TT) * CC + h * DD;

    // ---- load Q tile + KV tile 0 via cp.async ----
    #pragma unroll
    for (int i = 0; i < 4; i++) {
        int idx = tid + i * 256;                 // 0..1023
        int r = idx >> 3, ch = idx & 7;
        cpa16(smb + SQH + (uint32_t)(r * AST + ch * 16),
              g_qh + rowOff + (size_t)(qb + r) * CC + ch * 8);
    }
    auto stageKV = [&](int t, int bufi) {
        int kb = t * AKV;
        #pragma unroll
        for (int i = 0; i < 4; i++) {
            int idx = tid + i * 256;
            int mv = idx >> 9, r = (idx >> 3) & 63, ch = idx & 7;
            const __half* src = (mv ? g_vh : g_kh) + rowOff + (size_t)(kb + r) * CC + ch * 8;
            cpa16(smb + (mv ? SV0 : SK0) + (uint32_t)(bufi * (64 * AST) + r * AST + ch * 16), src);
        }
    };
    stageKV(0, 0);
    cpa_commit();
    cpa_wait<0>();
    __syncthreads();

    // ---- Q fragments (register resident) ----
    const uint32_t qlane = (uint32_t)((lane & 15) * AST + (lane >> 4) * 16);
    uint32_t qf[4][4];
    {
        const uint32_t qbase = smb + SQH + (uint32_t)(wid * 16 * AST) + qlane;
        #pragma unroll
        for (int ks = 0; ks < 4; ks++)
            ldsm4(qf[ks], qbase + ks * 32);
    }

    float O[8][4];
    #pragma unroll
    for (int i = 0; i < 8; i++)
        #pragma unroll
        for (int j = 0; j < 4; j++) O[i][j] = 0.f;
    float m0 = -1e30f, m1 = -1e30f, l0 = 0.f, l1 = 0.f;

    const int wr0 = qb + wid * 16;
    const int ntiles = qb / AKV + 2;
    const uint32_t klane = (uint32_t)(((lane & 7) + ((lane >> 4) & 1) * 8) * AST
                                      + ((lane >> 3) & 1) * 16);
    const uint32_t vlane = (uint32_t)(((lane & 7) + ((lane >> 3) & 1) * 8) * AST
                                      + ((lane >> 4) & 1) * 16);

    for (int t = 0; t < ntiles; t++) {
        const int bufi = t & 1;
        if (t + 1 < ntiles) {
            stageKV(t + 1, bufi ^ 1);
            cpa_commit();
            cpa_wait<1>();
        } else {
            cpa_wait<0>();
        }
        __syncthreads();

        const int kb = t * AKV;
        if (kb <= wr0 + 15) {
            // ---- scores S = Q . K^T (single term) ----
            float S[8][4];
            #pragma unroll
            for (int i = 0; i < 8; i++)
                #pragma unroll
                for (int j = 0; j < 4; j++) S[i][j] = 0.f;

            const uint32_t kbase = smb + SK0 + (uint32_t)(bufi * (64 * AST)) + klane;
            #pragma unroll
            for (int nn = 0; nn < 4; nn++)
                #pragma unroll
                for (int ks = 0; ks < 4; ks++) {
                    uint32_t kf[4];
                    ldsm4(kf, kbase + (uint32_t)(nn * 16 * AST + ks * 32));
                    mma16816h(S[2*nn],   qf[ks], kf[0], kf[1]);
                    mma16816h(S[2*nn+1], qf[ks], kf[2], kf[3]);
                }

            // ---- causal mask ----
            if (kb + 63 > wr0) {
                const int r0 = wr0 + (lane >> 2), r1 = r0 + 8;
                #pragma unroll
                for (int sf = 0; sf < 8; sf++) {
                    const int c = kb + sf * 8 + (lane & 3) * 2;
                    if (c     > r0) S[sf][0] = -1e30f;
                    if (c + 1 > r0) S[sf][1] = -1e30f;
                    if (c     > r1) S[sf][2] = -1e30f;
                    if (c + 1 > r1) S[sf][3] = -1e30f;
                }
            }

            // ---- online softmax (log2 domain) ----
            float mx0 = -1e30f, mx1 = -1e30f;
            #pragma unroll
            for (int sf = 0; sf < 8; sf++) {
                mx0 = fmaxf(mx0, fmaxf(S[sf][0], S[sf][1]));
                mx1 = fmaxf(mx1, fmaxf(S[sf][2], S[sf][3]));
            }
            mx0 = fmaxf(mx0, __shfl_xor_sync(0xffffffffu, mx0, 1));
            mx0 = fmaxf(mx0, __shfl_xor_sync(0xffffffffu, mx0, 2));
            mx1 = fmaxf(mx1, __shfl_xor_sync(0xffffffffu, mx1, 1));
            mx1 = fmaxf(mx1, __shfl_xor_sync(0xffffffffu, mx1, 2));
            const float nm0 = fmaxf(m0, mx0), nm1 = fmaxf(m1, mx1);
            const float corr0 = ex2f(m0 - nm0), corr1 = ex2f(m1 - nm1);
            m0 = nm0; m1 = nm1;

            float sum0 = 0.f, sum1 = 0.f;
            #pragma unroll
            for (int sf = 0; sf < 8; sf++) {
                S[sf][0] = ex2f(S[sf][0] - nm0);
                S[sf][1] = ex2f(S[sf][1] - nm0);
                S[sf][2] = ex2f(S[sf][2] - nm1);
                S[sf][3] = ex2f(S[sf][3] - nm1);
                sum0 += S[sf][0] + S[sf][1];
                sum1 += S[sf][2] + S[sf][3];
            }
            sum0 += __shfl_xor_sync(0xffffffffu, sum0, 1);
            sum0 += __shfl_xor_sync(0xffffffffu, sum0, 2);
            sum1 += __shfl_xor_sync(0xffffffffu, sum1, 1);
            sum1 += __shfl_xor_sync(0xffffffffu, sum1, 2);
            l0 = l0 * corr0 + sum0;
            l1 = l1 * corr1 + sum1;

            #pragma unroll
            for (int sf = 0; sf < 8; sf++) {
                O[sf][0] *= corr0; O[sf][1] *= corr0;
                O[sf][2] *= corr1; O[sf][3] *= corr1;
            }

            // ---- pack P into fp16 A-fragments (single term) ----
            uint32_t pa[4][4];
            #pragma unroll
            for (int j = 0; j < 4; j++) {
                #pragma unroll
                for (int q = 0; q < 4; q++) {
                    const int sf = 2 * j + (q >> 1);
                    const int e  = (q & 1) * 2;
                    pa[j][q] = packh2(S[sf][e], S[sf][e + 1]);
                }
            }

            // ---- O += P . V ----
            const uint32_t vbase = smb + SV0 + (uint32_t)(bufi * (64 * AST)) + vlane;
            #pragma unroll
            for (int dd = 0; dd < 4; dd++)
                #pragma unroll
                for (int j = 0; j < 4; j++) {
                    uint32_t vf[4];
                    ldsm4t(vf, vbase + (uint32_t)(j * 16 * AST + dd * 32));
                    mma16816h(O[2*dd],   pa[j], vf[0], vf[1]);
                    mma16816h(O[2*dd+1], pa[j], vf[2], vf[3]);
                }
        }
        __syncthreads();
    }

    // ---- epilogue: normalize, convert fp16, store into g_ah ----
    const float inv0 = 1.f / l0, inv1 = 1.f / l1;
    const int row0 = qb + wid * 16 + (lane >> 2);
    #pragma unroll
    for (int sf = 0; sf < 8; sf++) {
        const int col = h * DD + sf * 8 + (lane & 3) * 2;
        *(__half2*)(g_ah + (size_t)(b * TT + row0) * CC + col) =
            __floats2half2_rn(O[sf][0] * inv0, O[sf][1] * inv0);
        *(__half2*)(g_ah + (size_t)(b * TT + row0 + 8) * CC + col) =
            __floats2half2_rn(O[sf][2] * inv1, O[sf][3] * inv1);
    }
}

// ---------------------------------------------------------------------------
// Launch sequence
// ---------------------------------------------------------------------------
extern "C" void kernel_launch(void* const* d_in, const int* in_sizes, int n_in,
                              void* d_out, int out_size)
{
    const float* x  = (const float*)d_in[0];
    const float* Wq = (const float*)d_in[1];
    const float* bq = (const float*)d_in[2];
    const float* Wk = (const float*)d_in[3];
    const float* bk = (const float*)d_in[4];
    const float* Wv = (const float*)d_in[5];
    const float* bv = (const float*)d_in[6];
    const float* Wo = (const float*)d_in[7];
    const float* bo = (const float*)d_in[8];
    float* out = (float*)d_out;

    cudaFuncSetAttribute(gemm_fp16<true>,  cudaFuncAttributeMaxDynamicSharedMemorySize, GSMEM_TOTAL);
    cudaFuncSetAttribute(gemm_fp16<false>, cudaFuncAttributeMaxDynamicSharedMemorySize, GSMEM_TOTAL);
    cudaFuncSetAttribute(attn_tc,          cudaFuncAttributeMaxDynamicSharedMemorySize, ASMEM);

    const dim3 gcv(MM * CC / 4 / 256);
    const dim3 gtr(CC / 32, CC / 32, 4);
    const dim3 gqkv(CC / BN, MM / BM, 3);
    const dim3 go(CC / BN, MM / BM);

    cvt_x<<<gcv, 256>>>(x);
    cvt_wt_all<<<gtr, 256>>>(Wq, Wk, Wv, Wo);

    gemm_fp16<true><<<gqkv, 256, GSMEM_TOTAL>>>(bq, bk, bv, nullptr);

    const dim3 ga(TT / AQ, HH, BB);
    attn_tc<<<ga, 256, ASMEM>>>();

    gemm_fp16<false><<<go, 256, GSMEM_TOTAL>>>(bo, nullptr, nullptr, out);
}